// round 4
// baseline (speedup 1.0000x reference)
#include <cuda_runtime.h>
#include <cstdint>

// ---------------- problem constants ----------------
#define N_MAX 100000
#define E_MAX 1600000
#define IN_DIM 128
#define HID_DIM 128
#define OUT_DIM 64

typedef unsigned long long u64;

// ---------------- device scratch ----------------
__device__ int   g_is64;
__device__ int   g_esrc[E_MAX];
__device__ int   g_edst[E_MAX];
__device__ int   g_cnt[N_MAX];
__device__ int   g_rptr[N_MAX + 1];
__device__ int   g_cursor[N_MAX];
__device__ int   g_part[256];
__device__ float g_dinv[N_MAX];
__device__ int   g_csr[E_MAX];
__device__ __align__(16) float g_g1[(size_t)N_MAX * HID_DIM];   // x@W1 (unscaled)
__device__ __align__(16) float g_h1[(size_t)N_MAX * HID_DIM];   // relu output of layer 1
__device__ __align__(16) float g_g2[(size_t)N_MAX * OUT_DIM];   // h1@W2 (unscaled)

// ---------------- packed f32x2 helpers ----------------
__device__ __forceinline__ void fma2(u64& acc, u64 a, u64 b) {
    asm("fma.rn.f32x2 %0, %1, %2, %0;" : "+l"(acc) : "l"(a), "l"(b));
}

// ---------------- dtype detection & conversion ----------------
__global__ void k_detect(const void* p) {
    const long long* q = (const long long*)p;
    int ok = 1;
    for (int i = 0; i < 8; i++) {
        long long v = q[i];
        if (v < 0 || v >= (long long)N_MAX * 4) ok = 0;
    }
    g_is64 = ok;
}

// convert edge dtype AND zero the degree counters in one pass
__global__ void k_convert_zero(const void* p, int E, int n) {
    int e = blockIdx.x * blockDim.x + threadIdx.x;
    if (e < n) g_cnt[e] = 0;
    if (e >= E) return;
    int s, d;
    if (g_is64) {
        const long long* q = (const long long*)p;
        s = (int)q[e];
        d = (int)q[(size_t)E + e];
    } else {
        const int* q = (const int*)p;
        s = q[e];
        d = q[E + e];
    }
    g_esrc[e] = s;
    g_edst[e] = d;
}

// ---------------- CSR build ----------------
__global__ void k_count(int E) {
    int e = blockIdx.x * blockDim.x + threadIdx.x;
    if (e >= E) return;
    atomicAdd(&g_cnt[g_edst[e]], 1);
}

__global__ void k_scanA(int n) {
    __shared__ int sh[1024];
    int t = threadIdx.x;
    int idx = blockIdx.x * 1024 + t;
    int v = (idx < n) ? g_cnt[idx] : 0;
    sh[t] = v;
    __syncthreads();
#pragma unroll
    for (int off = 1; off < 1024; off <<= 1) {
        int add = (t >= off) ? sh[t - off] : 0;
        __syncthreads();
        sh[t] += add;
        __syncthreads();
    }
    int incl = sh[t];
    if (idx < n) g_rptr[idx] = incl - v;
    if (t == 1023) g_part[blockIdx.x] = incl;
}

__global__ void k_scanB(int nb) {
    if (threadIdx.x == 0 && blockIdx.x == 0) {
        int acc = 0;
        for (int i = 0; i < nb; i++) {
            int v = g_part[i];
            g_part[i] = acc;
            acc += v;
        }
    }
}

__global__ void k_scanC(int n, int E) {
    int idx = blockIdx.x * blockDim.x + threadIdx.x;
    if (idx < n) {
        int r = g_rptr[idx] + g_part[idx >> 10];
        g_rptr[idx] = r;
        g_cursor[idx] = r;
        g_dinv[idx] = rsqrtf((float)g_cnt[idx] + 1.0f);
    }
    if (idx == 0) g_rptr[n] = E;
}

__global__ void k_scatter(int E) {
    int e = blockIdx.x * blockDim.x + threadIdx.x;
    if (e >= E) return;
    int d = g_edst[e];
    int pos = atomicAdd(&g_cursor[d], 1);
    g_csr[pos] = g_esrc[e];
}

// ---------------- GEMM: G = X @ W, X [n,128], W [128,NC] ------------------
// K-paired FFMA2: each u64 accumulator = (even-k partial, odd-k partial).
// Both operands load as natural LDS.64 pairs -> zero dup MOVs.
//   xs [128][32]   row-major, k contiguous -> a pair = LDS.64 (broadcast).
//   ws_t[NC][34]   W transposed, pad 34 (8B-aligned rows, banks 2tx+k -> CF).
// 512 threads: thread tile 4 rows x 8 cols (cols = tx + 16j, lane-coalesced).
template <int NC>
__global__ __launch_bounds__(512) void k_gemm(
    const float* __restrict__ X, const float* __restrict__ W,
    float* __restrict__ G, int n)
{
    constexpr int BM = 128, BK = 32;
    constexpr int CPT = NC / 16;          // cols per thread (8 or 4)
    __shared__ float xs[BM][BK];
    __shared__ float ws_t[NC][34];

    int tid = threadIdx.x;
    int tx = tid & 15;
    int ty = tid >> 4;                    // 0..31
    int m0 = ty * 4;
    int mbase = blockIdx.x * BM;

    u64 acc[4][CPT];
#pragma unroll
    for (int i = 0; i < 4; i++)
#pragma unroll
        for (int j = 0; j < CPT; j++) acc[i][j] = 0ull;

    for (int kc = 0; kc < IN_DIM; kc += BK) {
        // X tile: 128 rows x 32 k = 1024 float4, coalesced + CF stores
#pragma unroll
        for (int r = 0; r < 2; r++) {
            int li = tid + r * 512;
            int m = li >> 3;
            int kq = li & 7;
            int row = mbase + m;
            float4 v = make_float4(0.f, 0.f, 0.f, 0.f);
            if (row < n) v = *(const float4*)(X + (size_t)row * IN_DIM + kc + kq * 4);
            *(float4*)&xs[m][kq * 4] = v;
        }
        // W tile transposed: 32 k x NC cols
        constexpr int WF4 = BK * NC / 4;
#pragma unroll
        for (int r = 0; r < (WF4 + 511) / 512; r++) {
            int li = tid + r * 512;
            if (WF4 % 512 == 0 || li < WF4) {
                int k = li / (NC / 4);
                int cq = li % (NC / 4);
                float4 v = *(const float4*)(W + (size_t)(kc + k) * NC + cq * 4);
                ws_t[cq * 4 + 0][k] = v.x;
                ws_t[cq * 4 + 1][k] = v.y;
                ws_t[cq * 4 + 2][k] = v.z;
                ws_t[cq * 4 + 3][k] = v.w;
            }
        }
        __syncthreads();

#pragma unroll
        for (int k = 0; k < BK; k += 2) {
            u64 a[4], b[CPT];
#pragma unroll
            for (int i = 0; i < 4; i++)
                a[i] = *(const u64*)&xs[m0 + i][k];
#pragma unroll
            for (int j = 0; j < CPT; j++)
                b[j] = *(const u64*)&ws_t[tx + 16 * j][k];
#pragma unroll
            for (int i = 0; i < 4; i++)
#pragma unroll
                for (int j = 0; j < CPT; j++)
                    fma2(acc[i][j], a[i], b[j]);
        }
        __syncthreads();
    }

    // epilogue: fold k-halves, store (lanes tx -> consecutive cols: coalesced)
#pragma unroll
    for (int i = 0; i < 4; i++) {
        int row = mbase + m0 + i;
        if (row < n) {
            float* go = G + (size_t)row * NC;
#pragma unroll
            for (int j = 0; j < CPT; j++) {
                float2 v = *(const float2*)&acc[i][j];
                go[tx + 16 * j] = v.x + v.y;
            }
        }
    }
}

// -------- aggregation: OUT[i] = act(dinv[i]*(sum_j dinv[j]*G[j] + dinv[i]*G[i]) + bias)
template <int NC, bool RELU>
__global__ __launch_bounds__(256) void k_agg(
    const float* __restrict__ G, const float* __restrict__ bias,
    float* __restrict__ OUT, int n)
{
    constexpr int V = NC / 32;            // floats per lane (4 or 2)
    int gw = (blockIdx.x * blockDim.x + threadIdx.x) >> 5;
    int lane = threadIdx.x & 31;
    if (gw >= n) return;

    float di = g_dinv[gw];

    float acc[V];
    const float* pself = G + (size_t)gw * NC + lane * V;
    if constexpr (V == 4) {
        float4 v = *(const float4*)pself;
        acc[0] = di * v.x; acc[1] = di * v.y; acc[2] = di * v.z; acc[3] = di * v.w;
    } else {
        float2 v = *(const float2*)pself;
        acc[0] = di * v.x; acc[1] = di * v.y;
    }

    int s = g_rptr[gw], e = g_rptr[gw + 1];
    for (int base = s; base < e; base += 32) {
        int idx = base + lane;
        int sj = 0;
        float dj = 0.0f;
        if (idx < e) {
            sj = g_csr[idx];
            dj = g_dinv[sj];
        }
        int m = e - base; if (m > 32) m = 32;
        int j = 0;
        for (; j + 4 <= m; j += 4) {
            int s0 = __shfl_sync(0xffffffffu, sj, j);
            int s1 = __shfl_sync(0xffffffffu, sj, j + 1);
            int s2 = __shfl_sync(0xffffffffu, sj, j + 2);
            int s3 = __shfl_sync(0xffffffffu, sj, j + 3);
            float d0 = __shfl_sync(0xffffffffu, dj, j);
            float d1 = __shfl_sync(0xffffffffu, dj, j + 1);
            float d2 = __shfl_sync(0xffffffffu, dj, j + 2);
            float d3 = __shfl_sync(0xffffffffu, dj, j + 3);
            if constexpr (V == 4) {
                float4 a = *(const float4*)(G + (size_t)s0 * NC + lane * 4);
                float4 b = *(const float4*)(G + (size_t)s1 * NC + lane * 4);
                float4 c = *(const float4*)(G + (size_t)s2 * NC + lane * 4);
                float4 d = *(const float4*)(G + (size_t)s3 * NC + lane * 4);
                acc[0] += d0 * a.x + d1 * b.x; acc[1] += d0 * a.y + d1 * b.y;
                acc[2] += d0 * a.z + d1 * b.z; acc[3] += d0 * a.w + d1 * b.w;
                acc[0] += d2 * c.x + d3 * d.x; acc[1] += d2 * c.y + d3 * d.y;
                acc[2] += d2 * c.z + d3 * d.z; acc[3] += d2 * c.w + d3 * d.w;
            } else {
                float2 a = *(const float2*)(G + (size_t)s0 * NC + lane * 2);
                float2 b = *(const float2*)(G + (size_t)s1 * NC + lane * 2);
                float2 c = *(const float2*)(G + (size_t)s2 * NC + lane * 2);
                float2 d = *(const float2*)(G + (size_t)s3 * NC + lane * 2);
                acc[0] += d0 * a.x + d1 * b.x; acc[1] += d0 * a.y + d1 * b.y;
                acc[0] += d2 * c.x + d3 * d.x; acc[1] += d2 * c.y + d3 * d.y;
            }
        }
        for (; j < m; j++) {
            int s0 = __shfl_sync(0xffffffffu, sj, j);
            float d0 = __shfl_sync(0xffffffffu, dj, j);
            const float* p = G + (size_t)s0 * NC + lane * V;
            if constexpr (V == 4) {
                float4 a = *(const float4*)p;
                acc[0] += d0 * a.x; acc[1] += d0 * a.y;
                acc[2] += d0 * a.z; acc[3] += d0 * a.w;
            } else {
                float2 a = *(const float2*)p;
                acc[0] += d0 * a.x; acc[1] += d0 * a.y;
            }
        }
    }

    float bv[V];
    if constexpr (V == 4) {
        float4 b = *(const float4*)(bias + lane * 4);
        bv[0] = b.x; bv[1] = b.y; bv[2] = b.z; bv[3] = b.w;
    } else {
        float2 b = *(const float2*)(bias + lane * 2);
        bv[0] = b.x; bv[1] = b.y;
    }
    float r[V];
#pragma unroll
    for (int v = 0; v < V; v++) {
        r[v] = acc[v] * di + bv[v];
        if (RELU) r[v] = fmaxf(r[v], 0.0f);
    }
    float* po = OUT + (size_t)gw * NC + lane * V;
    if constexpr (V == 4) {
        float4 o; o.x = r[0]; o.y = r[1]; o.z = r[2]; o.w = r[3];
        *(float4*)po = o;
    } else {
        float2 o; o.x = r[0]; o.y = r[1];
        *(float2*)po = o;
    }
}

// ---------------- launch ----------------
extern "C" void kernel_launch(void* const* d_in, const int* in_sizes, int n_in,
                              void* d_out, int out_size)
{
    const float* x  = (const float*)d_in[0];
    const void*  ei = d_in[1];
    const float* W1 = (const float*)d_in[2];
    const float* b1 = (const float*)d_in[3];
    const float* W2 = (const float*)d_in[4];
    const float* b2 = (const float*)d_in[5];
    float* out = (float*)d_out;

    int n = in_sizes[0] / IN_DIM;
    int E = in_sizes[1] / 2;

    float *g1p, *h1p, *g2p;
    cudaGetSymbolAddress((void**)&g1p, g_g1);
    cudaGetSymbolAddress((void**)&h1p, g_h1);
    cudaGetSymbolAddress((void**)&g2p, g_g2);

    int nb1024 = (n + 1023) / 1024;
    int mEn = (E > n) ? E : n;

    // gemm1 independent of CSR chain -> launch index 3 (ncu's capture slot)
    k_detect<<<1, 1>>>(ei);
    k_convert_zero<<<(mEn + 255) / 256, 256>>>(ei, E, n);
    k_count<<<(E + 255) / 256, 256>>>(E);
    k_gemm<HID_DIM><<<(n + 127) / 128, 512>>>(x, W1, g1p, n);

    k_scanA<<<nb1024, 1024>>>(n);
    k_scanB<<<1, 32>>>(nb1024);
    k_scanC<<<(n + 255) / 256, 256>>>(n, E);
    k_scatter<<<(E + 255) / 256, 256>>>(E);

    k_agg<HID_DIM, true><<<(n * 32 + 255) / 256, 256>>>(g1p, b1, h1p, n);
    k_gemm<OUT_DIM><<<(n + 127) / 128, 512>>>(h1p, W2, g2p, n);
    k_agg<OUT_DIM, false><<<(n * 32 + 255) / 256, 256>>>(g2p, b2, out, n);
}

// round 6
// speedup vs baseline: 1.2767x; 1.2767x over previous
#include <cuda_runtime.h>
#include <cuda_bf16.h>
#include <cstdint>

// ---------------- problem constants ----------------
#define N_MAX 100000
#define E_MAX 1600000
#define IN_DIM 128
#define HID_DIM 128
#define OUT_DIM 64

typedef unsigned long long u64;

// ---------------- device scratch ----------------
__device__ int   g_is64;
__device__ int   g_esrc[E_MAX];
__device__ int   g_edst[E_MAX];
__device__ int   g_cnt[N_MAX];
__device__ int   g_rptr[N_MAX + 1];
__device__ int   g_cursor[N_MAX];
__device__ int   g_part[256];
__device__ float g_dinv[N_MAX];
__device__ int   g_csr[E_MAX];
__device__ __align__(16) float g_g1[(size_t)N_MAX * HID_DIM];   // x@W1
__device__ __align__(16) float g_h1[(size_t)N_MAX * HID_DIM];   // relu layer-1 out
__device__ __align__(16) float g_g2[(size_t)N_MAX * OUT_DIM];   // h1@W2

// ---------------- PTX helpers (baseline ISA only: ldmatrix + mma.sync) ------
__device__ __forceinline__ uint32_t smem_u32(const void* p) {
    uint32_t a;
    asm("{ .reg .u64 t; cvta.to.shared.u64 t, %1; cvt.u32.u64 %0, t; }" : "=r"(a) : "l"(p));
    return a;
}
__device__ __forceinline__ void ldsm4(uint32_t* r, uint32_t addr) {
    asm volatile("ldmatrix.sync.aligned.m8n8.x4.shared.b16 {%0,%1,%2,%3}, [%4];"
                 : "=r"(r[0]), "=r"(r[1]), "=r"(r[2]), "=r"(r[3]) : "r"(addr));
}
__device__ __forceinline__ void mma_bf16(float* c, const uint32_t* a, const uint32_t* b) {
    asm volatile(
        "mma.sync.aligned.m16n8k16.row.col.f32.bf16.bf16.f32 "
        "{%0,%1,%2,%3}, {%4,%5,%6,%7}, {%8,%9}, {%0,%1,%2,%3};"
        : "+f"(c[0]), "+f"(c[1]), "+f"(c[2]), "+f"(c[3])
        : "r"(a[0]), "r"(a[1]), "r"(a[2]), "r"(a[3]), "r"(b[0]), "r"(b[1]));
}
__device__ __forceinline__ uint32_t pack2(__nv_bfloat16 a, __nv_bfloat16 b) {
    return (uint32_t)__bfloat16_as_ushort(a) | ((uint32_t)__bfloat16_as_ushort(b) << 16);
}

// ---------------- dtype detection & conversion ----------------
__global__ void k_detect(const void* p) {
    const long long* q = (const long long*)p;
    int ok = 1;
    for (int i = 0; i < 8; i++) {
        long long v = q[i];
        if (v < 0 || v >= (long long)N_MAX * 4) ok = 0;
    }
    g_is64 = ok;
}

__global__ void k_convert_zero(const void* p, int E, int n) {
    int e = blockIdx.x * blockDim.x + threadIdx.x;
    if (e < n) g_cnt[e] = 0;
    if (e >= E) return;
    int s, d;
    if (g_is64) {
        const long long* q = (const long long*)p;
        s = (int)q[e];
        d = (int)q[(size_t)E + e];
    } else {
        const int* q = (const int*)p;
        s = q[e];
        d = q[E + e];
    }
    g_esrc[e] = s;
    g_edst[e] = d;
}

// ---------------- CSR build ----------------
__global__ void k_count(int E) {
    int e = blockIdx.x * blockDim.x + threadIdx.x;
    if (e >= E) return;
    atomicAdd(&g_cnt[g_edst[e]], 1);
}

__global__ void k_scanA(int n) {
    __shared__ int sh[1024];
    int t = threadIdx.x;
    int idx = blockIdx.x * 1024 + t;
    int v = (idx < n) ? g_cnt[idx] : 0;
    sh[t] = v;
    __syncthreads();
#pragma unroll
    for (int off = 1; off < 1024; off <<= 1) {
        int add = (t >= off) ? sh[t - off] : 0;
        __syncthreads();
        sh[t] += add;
        __syncthreads();
    }
    int incl = sh[t];
    if (idx < n) g_rptr[idx] = incl - v;
    if (t == 1023) g_part[blockIdx.x] = incl;
}

__global__ void k_scanB(int nb) {
    if (threadIdx.x == 0 && blockIdx.x == 0) {
        int acc = 0;
        for (int i = 0; i < nb; i++) {
            int v = g_part[i];
            g_part[i] = acc;
            acc += v;
        }
    }
}

__global__ void k_scanC(int n, int E) {
    int idx = blockIdx.x * blockDim.x + threadIdx.x;
    if (idx < n) {
        int r = g_rptr[idx] + g_part[idx >> 10];
        g_rptr[idx] = r;
        g_cursor[idx] = r;
        g_dinv[idx] = rsqrtf((float)g_cnt[idx] + 1.0f);
    }
    if (idx == 0) g_rptr[n] = E;
}

__global__ void k_scatter(int E) {
    int e = blockIdx.x * blockDim.x + threadIdx.x;
    if (e >= E) return;
    int d = g_edst[e];
    int pos = atomicAdd(&g_cursor[d], 1);
    g_csr[pos] = g_esrc[e];
}

// ---------------- GEMM: G = X @ W via split-bf16 mma.sync -----------------
// X [n,128] fp32 -> A_hi/A_lo bf16 smem tiles [128][136] (272B pitch).
// W [128,NC] fp32 -> Wt_hi/Wt_lo bf16 smem [NC][136] (B col-major = Wt row-major).
// acc (fp32) += Ah*Bh + Ah*Bl + Al*Bh  (lo*lo term ~2^-18, dropped).
// 8 warps: 2(m) x 4(n), warp tile 64 x NC/4, k-steps of 16.
template <int NC>
__global__ __launch_bounds__(256) void k_gemm_mma(
    const float* __restrict__ X, const float* __restrict__ W,
    float* __restrict__ G, int n)
{
    extern __shared__ char smem[];
    constexpr int PITCH = 272;                 // 136 bf16 per row
    constexpr int AH = 0;
    constexpr int AL = AH + 128 * PITCH;       // 34816
    constexpr int BH = AL + 128 * PITCH;       // 69632
    constexpr int BL = BH + NC * PITCH;
    constexpr int NF = NC / 32;                // n8 frags per warp (4 or 2)

    uint32_t sb = smem_u32(smem);
    int tid = threadIdx.x;
    int mbase = blockIdx.x * 128;

    // ---- A: load X rows, Sterbenz-split to bf16 hi/lo ----
    {
        int r = tid >> 1;
        int kh = (tid & 1) * 64;
        int row = mbase + r;
        char* ahp = smem + AH + r * PITCH;
        char* alp = smem + AL + r * PITCH;
#pragma unroll
        for (int k = kh; k < kh + 64; k += 4) {
            float4 v = make_float4(0.f, 0.f, 0.f, 0.f);
            if (row < n) v = *(const float4*)(X + (size_t)row * IN_DIM + k);
            __nv_bfloat16 h0 = __float2bfloat16_rn(v.x);
            __nv_bfloat16 h1 = __float2bfloat16_rn(v.y);
            __nv_bfloat16 h2 = __float2bfloat16_rn(v.z);
            __nv_bfloat16 h3 = __float2bfloat16_rn(v.w);
            __nv_bfloat16 l0 = __float2bfloat16_rn(v.x - __bfloat162float(h0));
            __nv_bfloat16 l1 = __float2bfloat16_rn(v.y - __bfloat162float(h1));
            __nv_bfloat16 l2 = __float2bfloat16_rn(v.z - __bfloat162float(h2));
            __nv_bfloat16 l3 = __float2bfloat16_rn(v.w - __bfloat162float(h3));
            uint2 hv; hv.x = pack2(h0, h1); hv.y = pack2(h2, h3);
            uint2 lv; lv.x = pack2(l0, l1); lv.y = pack2(l2, l3);
            *(uint2*)(ahp + k * 2) = hv;
            *(uint2*)(alp + k * 2) = lv;
        }
    }
    // ---- B: Wt[c][k] = W[k][c], split hi/lo ----
    {
        int c = tid & (NC - 1);
        int kcount = 128 / (256 / NC);         // 64 (NC=128) or 32 (NC=64)
        int k0 = (tid / NC) * kcount;
        char* bhp = smem + BH + c * PITCH;
        char* blp = smem + BL + c * PITCH;
        for (int k = k0; k < k0 + kcount; k++) {
            float w = W[(size_t)k * NC + c];
            __nv_bfloat16 h = __float2bfloat16_rn(w);
            __nv_bfloat16 l = __float2bfloat16_rn(w - __bfloat162float(h));
            *(__nv_bfloat16*)(bhp + k * 2) = h;
            *(__nv_bfloat16*)(blp + k * 2) = l;
        }
    }
    __syncthreads();

    int wid = tid >> 5;
    int lane = tid & 31;
    int wm = wid & 1;
    int wn = wid >> 1;
    int m0 = wm * 64;
    int n0 = wn * (NC / 4);

    float acc[4][NF][4];
#pragma unroll
    for (int mi = 0; mi < 4; mi++)
#pragma unroll
        for (int nf = 0; nf < NF; nf++)
#pragma unroll
            for (int q = 0; q < 4; q++) acc[mi][nf][q] = 0.0f;

    // ldmatrix lane addressing
    uint32_t a_addr0 = sb + AH + (uint32_t)(m0 + (lane & 15)) * PITCH + ((lane >> 4) * 16);
    uint32_t b_row   = (uint32_t)(n0 + (lane & 7) + ((lane >> 4) & 1) * 8);
    uint32_t b_addr0 = sb + BH + b_row * PITCH + (((lane >> 3) & 1) * 16);

#pragma unroll
    for (int ks = 0; ks < 8; ks++) {
        uint32_t koff = ks * 32;
        uint32_t ah[4][4], al[4][4];
#pragma unroll
        for (int mi = 0; mi < 4; mi++) {
            ldsm4(ah[mi], a_addr0 + mi * 16 * PITCH + koff);
            ldsm4(al[mi], a_addr0 + (AL - AH) + mi * 16 * PITCH + koff);
        }
        uint32_t bh[NF][2], bl[NF][2];
#pragma unroll
        for (int pr = 0; pr < NF / 2; pr++) {
            uint32_t r[4];
            ldsm4(r, b_addr0 + pr * 16 * PITCH + koff);
            bh[2 * pr][0] = r[0]; bh[2 * pr][1] = r[1];
            bh[2 * pr + 1][0] = r[2]; bh[2 * pr + 1][1] = r[3];
            ldsm4(r, b_addr0 + (BL - BH) + pr * 16 * PITCH + koff);
            bl[2 * pr][0] = r[0]; bl[2 * pr][1] = r[1];
            bl[2 * pr + 1][0] = r[2]; bl[2 * pr + 1][1] = r[3];
        }
#pragma unroll
        for (int mi = 0; mi < 4; mi++)
#pragma unroll
            for (int nf = 0; nf < NF; nf++) {
                mma_bf16(acc[mi][nf], ah[mi], bh[nf]);
                mma_bf16(acc[mi][nf], ah[mi], bl[nf]);
                mma_bf16(acc[mi][nf], al[mi], bh[nf]);
            }
    }

    // ---- epilogue: m16n8 D frag -> fp32 G ----
#pragma unroll
    for (int mi = 0; mi < 4; mi++) {
        int r0 = mbase + m0 + mi * 16 + (lane >> 2);
#pragma unroll
        for (int nf = 0; nf < NF; nf++) {
            int col = n0 + nf * 8 + 2 * (lane & 3);
            if (r0 < n) {
                float2 v; v.x = acc[mi][nf][0]; v.y = acc[mi][nf][1];
                *(float2*)(G + (size_t)r0 * NC + col) = v;
            }
            if (r0 + 8 < n) {
                float2 v; v.x = acc[mi][nf][2]; v.y = acc[mi][nf][3];
                *(float2*)(G + (size_t)(r0 + 8) * NC + col) = v;
            }
        }
    }
}

// -------- aggregation: OUT[i] = act(dinv[i]*(sum_j dinv[j]*G[j] + dinv[i]*G[i]) + bias)
template <int NC, bool RELU>
__global__ __launch_bounds__(256) void k_agg(
    const float* __restrict__ G, const float* __restrict__ bias,
    float* __restrict__ OUT, int n)
{
    constexpr int V = NC / 32;
    int gw = (blockIdx.x * blockDim.x + threadIdx.x) >> 5;
    int lane = threadIdx.x & 31;
    if (gw >= n) return;

    float di = g_dinv[gw];

    float acc[V];
    const float* pself = G + (size_t)gw * NC + lane * V;
    if constexpr (V == 4) {
        float4 v = *(const float4*)pself;
        acc[0] = di * v.x; acc[1] = di * v.y; acc[2] = di * v.z; acc[3] = di * v.w;
    } else {
        float2 v = *(const float2*)pself;
        acc[0] = di * v.x; acc[1] = di * v.y;
    }

    int s = g_rptr[gw], e = g_rptr[gw + 1];
    for (int base = s; base < e; base += 32) {
        int idx = base + lane;
        int sj = 0;
        float dj = 0.0f;
        if (idx < e) {
            sj = g_csr[idx];
            dj = g_dinv[sj];
        }
        int m = e - base; if (m > 32) m = 32;
        int j = 0;
        for (; j + 4 <= m; j += 4) {
            int s0 = __shfl_sync(0xffffffffu, sj, j);
            int s1 = __shfl_sync(0xffffffffu, sj, j + 1);
            int s2 = __shfl_sync(0xffffffffu, sj, j + 2);
            int s3 = __shfl_sync(0xffffffffu, sj, j + 3);
            float d0 = __shfl_sync(0xffffffffu, dj, j);
            float d1 = __shfl_sync(0xffffffffu, dj, j + 1);
            float d2 = __shfl_sync(0xffffffffu, dj, j + 2);
            float d3 = __shfl_sync(0xffffffffu, dj, j + 3);
            if constexpr (V == 4) {
                float4 a = *(const float4*)(G + (size_t)s0 * NC + lane * 4);
                float4 b = *(const float4*)(G + (size_t)s1 * NC + lane * 4);
                float4 c = *(const float4*)(G + (size_t)s2 * NC + lane * 4);
                float4 d = *(const float4*)(G + (size_t)s3 * NC + lane * 4);
                acc[0] += d0 * a.x + d1 * b.x; acc[1] += d0 * a.y + d1 * b.y;
                acc[2] += d0 * a.z + d1 * b.z; acc[3] += d0 * a.w + d1 * b.w;
                acc[0] += d2 * c.x + d3 * d.x; acc[1] += d2 * c.y + d3 * d.y;
                acc[2] += d2 * c.z + d3 * d.z; acc[3] += d2 * c.w + d3 * d.w;
            } else {
                float2 a = *(const float2*)(G + (size_t)s0 * NC + lane * 2);
                float2 b = *(const float2*)(G + (size_t)s1 * NC + lane * 2);
                float2 c = *(const float2*)(G + (size_t)s2 * NC + lane * 2);
                float2 d = *(const float2*)(G + (size_t)s3 * NC + lane * 2);
                acc[0] += d0 * a.x + d1 * b.x; acc[1] += d0 * a.y + d1 * b.y;
                acc[0] += d2 * c.x + d3 * d.x; acc[1] += d2 * c.y + d3 * d.y;
            }
        }
        for (; j < m; j++) {
            int s0 = __shfl_sync(0xffffffffu, sj, j);
            float d0 = __shfl_sync(0xffffffffu, dj, j);
            const float* p = G + (size_t)s0 * NC + lane * V;
            if constexpr (V == 4) {
                float4 a = *(const float4*)p;
                acc[0] += d0 * a.x; acc[1] += d0 * a.y;
                acc[2] += d0 * a.z; acc[3] += d0 * a.w;
            } else {
                float2 a = *(const float2*)p;
                acc[0] += d0 * a.x; acc[1] += d0 * a.y;
            }
        }
    }

    float bv[V];
    if constexpr (V == 4) {
        float4 b = *(const float4*)(bias + lane * 4);
        bv[0] = b.x; bv[1] = b.y; bv[2] = b.z; bv[3] = b.w;
    } else {
        float2 b = *(const float2*)(bias + lane * 2);
        bv[0] = b.x; bv[1] = b.y;
    }
    float r[V];
#pragma unroll
    for (int v = 0; v < V; v++) {
        r[v] = acc[v] * di + bv[v];
        if (RELU) r[v] = fmaxf(r[v], 0.0f);
    }
    float* po = OUT + (size_t)gw * NC + lane * V;
    if constexpr (V == 4) {
        float4 o; o.x = r[0]; o.y = r[1]; o.z = r[2]; o.w = r[3];
        *(float4*)po = o;
    } else {
        float2 o; o.x = r[0]; o.y = r[1];
        *(float2*)po = o;
    }
}

// ---------------- launch ----------------
extern "C" void kernel_launch(void* const* d_in, const int* in_sizes, int n_in,
                              void* d_out, int out_size)
{
    const float* x  = (const float*)d_in[0];
    const void*  ei = d_in[1];
    const float* W1 = (const float*)d_in[2];
    const float* b1 = (const float*)d_in[3];
    const float* W2 = (const float*)d_in[4];
    const float* b2 = (const float*)d_in[5];
    float* out = (float*)d_out;

    int n = in_sizes[0] / IN_DIM;
    int E = in_sizes[1] / 2;

    float *g1p, *h1p, *g2p;
    cudaGetSymbolAddress((void**)&g1p, g_g1);
    cudaGetSymbolAddress((void**)&h1p, g_h1);
    cudaGetSymbolAddress((void**)&g2p, g_g2);

    // smem: A hi/lo (2*34816) + B hi/lo (2*NC*272)
    const int smem1 = 2 * 34816 + 2 * 128 * 272;   // 139264
    const int smem2 = 2 * 34816 + 2 * 64 * 272;    // 104448
    cudaFuncSetAttribute(k_gemm_mma<HID_DIM>, cudaFuncAttributeMaxDynamicSharedMemorySize, smem1);
    cudaFuncSetAttribute(k_gemm_mma<OUT_DIM>, cudaFuncAttributeMaxDynamicSharedMemorySize, smem2);

    int nb1024 = (n + 1023) / 1024;
    int mEn = (E > n) ? E : n;
    int ngrid = (n + 127) / 128;

    // gemm1 independent of CSR chain -> launch index 3 (ncu's capture slot)
    k_detect<<<1, 1>>>(ei);
    k_convert_zero<<<(mEn + 255) / 256, 256>>>(ei, E, n);
    k_count<<<(E + 255) / 256, 256>>>(E);
    k_gemm_mma<HID_DIM><<<ngrid, 256, smem1>>>(x, W1, g1p, n);

    k_scanA<<<nb1024, 1024>>>(n);
    k_scanB<<<1, 32>>>(nb1024);
    k_scanC<<<(n + 255) / 256, 256>>>(n, E);
    k_scatter<<<(E + 255) / 256, 256>>>(E);

    k_agg<HID_DIM, true><<<(n * 32 + 255) / 256, 256>>>(g1p, b1, h1p, n);
    k_gemm_mma<OUT_DIM><<<ngrid, 256, smem2>>>(h1p, W2, g2p, n);
    k_agg<OUT_DIM, false><<<(n * 32 + 255) / 256, 256>>>(g2p, b2, out, n);
}

// round 7
// speedup vs baseline: 1.3383x; 1.0482x over previous
#include <cuda_runtime.h>
#include <cuda_bf16.h>
#include <cstdint>

// ---------------- problem constants ----------------
#define N_MAX 100000
#define E_MAX 1600000
#define IN_DIM 128
#define HID_DIM 128
#define OUT_DIM 64

typedef unsigned long long u64;

// ---------------- device scratch ----------------
__device__ int   g_is64;
__device__ int   g_esrc[E_MAX];
__device__ int   g_edst[E_MAX];
__device__ int   g_cnt[N_MAX];
__device__ int   g_rptr[N_MAX + 1];
__device__ int   g_cursor[N_MAX];
__device__ int   g_part[256];
__device__ float g_dinv[N_MAX];
__device__ int   g_csr[E_MAX];
__device__ __align__(16) float g_g1[(size_t)N_MAX * HID_DIM];
__device__ __align__(16) float g_h1[(size_t)N_MAX * HID_DIM];
__device__ __align__(16) float g_g2[(size_t)N_MAX * OUT_DIM];
// pre-split weights, layout Wt[c][k] (k contiguous), hi block then lo block
__device__ __align__(16) __nv_bfloat16 g_w1s[2 * HID_DIM * IN_DIM];
__device__ __align__(16) __nv_bfloat16 g_w2s[2 * OUT_DIM * HID_DIM];

// ---------------- PTX helpers (baseline ISA: ldmatrix + mma.sync) ----------
__device__ __forceinline__ uint32_t smem_u32(const void* p) {
    uint32_t a;
    asm("{ .reg .u64 t; cvta.to.shared.u64 t, %1; cvt.u32.u64 %0, t; }" : "=r"(a) : "l"(p));
    return a;
}
__device__ __forceinline__ void ldsm4(uint32_t* r, uint32_t addr) {
    asm volatile("ldmatrix.sync.aligned.m8n8.x4.shared.b16 {%0,%1,%2,%3}, [%4];"
                 : "=r"(r[0]), "=r"(r[1]), "=r"(r[2]), "=r"(r[3]) : "r"(addr));
}
__device__ __forceinline__ void mma_bf16(float* c, const uint32_t* a, const uint32_t* b) {
    asm volatile(
        "mma.sync.aligned.m16n8k16.row.col.f32.bf16.bf16.f32 "
        "{%0,%1,%2,%3}, {%4,%5,%6,%7}, {%8,%9}, {%0,%1,%2,%3};"
        : "+f"(c[0]), "+f"(c[1]), "+f"(c[2]), "+f"(c[3])
        : "r"(a[0]), "r"(a[1]), "r"(a[2]), "r"(a[3]), "r"(b[0]), "r"(b[1]));
}
__device__ __forceinline__ uint32_t pack2(__nv_bfloat16 a, __nv_bfloat16 b) {
    return (uint32_t)__bfloat16_as_ushort(a) | ((uint32_t)__bfloat16_as_ushort(b) << 16);
}

// ---------------- dtype detection / zero ----------------
__global__ void k_detect(const void* p) {
    const long long* q = (const long long*)p;
    int ok = 1;
    for (int i = 0; i < 8; i++) {
        long long v = q[i];
        if (v < 0 || v >= (long long)N_MAX * 4) ok = 0;
    }
    g_is64 = ok;
}

__global__ void k_zero(int n) {
    int i = blockIdx.x * blockDim.x + threadIdx.x;
    if (i < n) g_cnt[i] = 0;
}

// ---------------- weight pre-split: W[k][c] -> Wt hi/lo [c][k] bf16 --------
__global__ void k_prepw(const float* __restrict__ W1, const float* __restrict__ W2) {
    int i = blockIdx.x * blockDim.x + threadIdx.x;
    if (i < HID_DIM * IN_DIM) {
        int c = i >> 7, k = i & 127;
        float w = W1[(size_t)k * HID_DIM + c];
        __nv_bfloat16 h = __float2bfloat16_rn(w);
        __nv_bfloat16 l = __float2bfloat16_rn(w - __bfloat162float(h));
        g_w1s[c * IN_DIM + k] = h;
        g_w1s[HID_DIM * IN_DIM + c * IN_DIM + k] = l;
    } else if (i < HID_DIM * IN_DIM + OUT_DIM * HID_DIM) {
        int j = i - HID_DIM * IN_DIM;
        int c = j >> 7, k = j & 127;
        float w = W2[(size_t)k * OUT_DIM + c];
        __nv_bfloat16 h = __float2bfloat16_rn(w);
        __nv_bfloat16 l = __float2bfloat16_rn(w - __bfloat162float(h));
        g_w2s[c * HID_DIM + k] = h;
        g_w2s[OUT_DIM * HID_DIM + c * HID_DIM + k] = l;
    }
}

// ---------------- convert + count fused ----------------
__global__ void k_convcnt(const void* p, int E) {
    int e = blockIdx.x * blockDim.x + threadIdx.x;
    if (e >= E) return;
    int s, d;
    if (g_is64) {
        const long long* q = (const long long*)p;
        s = (int)q[e];
        d = (int)q[(size_t)E + e];
    } else {
        const int* q = (const int*)p;
        s = q[e];
        d = q[E + e];
    }
    g_esrc[e] = s;
    g_edst[e] = d;
    atomicAdd(&g_cnt[d], 1);
}

// ---------------- scan / scatter ----------------
__global__ void k_scanA(int n) {
    __shared__ int sh[1024];
    int t = threadIdx.x;
    int idx = blockIdx.x * 1024 + t;
    int v = (idx < n) ? g_cnt[idx] : 0;
    sh[t] = v;
    __syncthreads();
#pragma unroll
    for (int off = 1; off < 1024; off <<= 1) {
        int add = (t >= off) ? sh[t - off] : 0;
        __syncthreads();
        sh[t] += add;
        __syncthreads();
    }
    int incl = sh[t];
    if (idx < n) g_rptr[idx] = incl - v;
    if (t == 1023) g_part[blockIdx.x] = incl;
}

__global__ void k_scanB(int nb) {
    if (threadIdx.x == 0 && blockIdx.x == 0) {
        int acc = 0;
        for (int i = 0; i < nb; i++) {
            int v = g_part[i];
            g_part[i] = acc;
            acc += v;
        }
    }
}

__global__ void k_scanC(int n, int E) {
    int idx = blockIdx.x * blockDim.x + threadIdx.x;
    if (idx < n) {
        int r = g_rptr[idx] + g_part[idx >> 10];
        g_rptr[idx] = r;
        g_cursor[idx] = r;
        g_dinv[idx] = rsqrtf((float)g_cnt[idx] + 1.0f);
    }
    if (idx == 0) g_rptr[n] = E;
}

__global__ void k_scatter(int E) {
    int e = blockIdx.x * blockDim.x + threadIdx.x;
    if (e >= E) return;
    int d = g_edst[e];
    int pos = atomicAdd(&g_cursor[d], 1);
    g_csr[pos] = g_esrc[e];
}

// ---------------- GEMM: G = X @ W via split-bf16 mma.sync ------------------
// M-tile 64 rows (2-3 CTAs/SM). A split in-kernel; B copied from pre-split
// gmem (pure uint4 copy). smem rows pitch 272B (ldmatrix conflict-free).
template <int NC>
__global__ __launch_bounds__(256) void k_gemm_mma(
    const float* __restrict__ X, const __nv_bfloat16* __restrict__ Ws,
    float* __restrict__ G, int n)
{
    extern __shared__ char smem[];
    constexpr int PITCH = 272;
    constexpr int BM = 64;
    constexpr int AH = 0;
    constexpr int AL = AH + BM * PITCH;        // 17408
    constexpr int BH = AL + BM * PITCH;        // 34816
    constexpr int BL = BH + NC * PITCH;
    constexpr int NF = NC / 32;                // n8 frags per warp (4 or 2)

    uint32_t sb = smem_u32(smem);
    int tid = threadIdx.x;
    int mbase = blockIdx.x * BM;

    // ---- A: load X rows (64 x 128 fp32), split to bf16 hi/lo ----
    {
        int r = tid >> 2;                      // 0..63
        int k0 = (tid & 3) * 32;
        int row = mbase + r;
        char* ahp = smem + AH + r * PITCH;
        char* alp = smem + AL + r * PITCH;
#pragma unroll
        for (int k = k0; k < k0 + 32; k += 4) {
            float4 v = make_float4(0.f, 0.f, 0.f, 0.f);
            if (row < n) v = *(const float4*)(X + (size_t)row * IN_DIM + k);
            __nv_bfloat16 h0 = __float2bfloat16_rn(v.x);
            __nv_bfloat16 h1 = __float2bfloat16_rn(v.y);
            __nv_bfloat16 h2 = __float2bfloat16_rn(v.z);
            __nv_bfloat16 h3 = __float2bfloat16_rn(v.w);
            __nv_bfloat16 l0 = __float2bfloat16_rn(v.x - __bfloat162float(h0));
            __nv_bfloat16 l1 = __float2bfloat16_rn(v.y - __bfloat162float(h1));
            __nv_bfloat16 l2 = __float2bfloat16_rn(v.z - __bfloat162float(h2));
            __nv_bfloat16 l3 = __float2bfloat16_rn(v.w - __bfloat162float(h3));
            uint2 hv; hv.x = pack2(h0, h1); hv.y = pack2(h2, h3);
            uint2 lv; lv.x = pack2(l0, l1); lv.y = pack2(l2, l3);
            *(uint2*)(ahp + k * 2) = hv;
            *(uint2*)(alp + k * 2) = lv;
        }
    }
    // ---- B: copy pre-split Wt hi/lo (NC x 128 bf16 each) ----
    {
        constexpr int BU4 = NC * 128 * 2 / 16;   // uint4 count per block (2048/1024)
        const uint4* ws4 = (const uint4*)Ws;
#pragma unroll
        for (int r = 0; r < BU4 / 256; r++) {
            int li = tid + r * 256;
            int c = li >> 4;
            int ch = li & 15;
            *(uint4*)(smem + BH + c * PITCH + ch * 16) = ws4[li];
            *(uint4*)(smem + BL + c * PITCH + ch * 16) = ws4[BU4 + li];
        }
    }
    __syncthreads();

    int wid = tid >> 5;
    int lane = tid & 31;
    int wm = wid & 1;
    int wn = wid >> 1;
    int m0 = wm * 32;
    int n0 = wn * (NC / 4);

    float acc[2][NF][4];
#pragma unroll
    for (int mi = 0; mi < 2; mi++)
#pragma unroll
        for (int nf = 0; nf < NF; nf++)
#pragma unroll
            for (int q = 0; q < 4; q++) acc[mi][nf][q] = 0.0f;

    uint32_t a_addr0 = sb + AH + (uint32_t)(m0 + (lane & 15)) * PITCH + ((lane >> 4) * 16);
    uint32_t b_row   = (uint32_t)(n0 + (lane & 7) + ((lane >> 4) & 1) * 8);
    uint32_t b_addr0 = sb + BH + b_row * PITCH + (((lane >> 3) & 1) * 16);

#pragma unroll
    for (int ks = 0; ks < 8; ks++) {
        uint32_t koff = ks * 32;
        uint32_t ah[2][4], al[2][4];
#pragma unroll
        for (int mi = 0; mi < 2; mi++) {
            ldsm4(ah[mi], a_addr0 + mi * 16 * PITCH + koff);
            ldsm4(al[mi], a_addr0 + (AL - AH) + mi * 16 * PITCH + koff);
        }
        uint32_t bh[NF][2], bl[NF][2];
#pragma unroll
        for (int pr = 0; pr < NF / 2; pr++) {
            uint32_t r[4];
            ldsm4(r, b_addr0 + pr * 16 * PITCH + koff);
            bh[2 * pr][0] = r[0]; bh[2 * pr][1] = r[1];
            bh[2 * pr + 1][0] = r[2]; bh[2 * pr + 1][1] = r[3];
            ldsm4(r, b_addr0 + (BL - BH) + pr * 16 * PITCH + koff);
            bl[2 * pr][0] = r[0]; bl[2 * pr][1] = r[1];
            bl[2 * pr + 1][0] = r[2]; bl[2 * pr + 1][1] = r[3];
        }
#pragma unroll
        for (int mi = 0; mi < 2; mi++)
#pragma unroll
            for (int nf = 0; nf < NF; nf++) {
                mma_bf16(acc[mi][nf], ah[mi], bh[nf]);
                mma_bf16(acc[mi][nf], ah[mi], bl[nf]);
                mma_bf16(acc[mi][nf], al[mi], bh[nf]);
            }
    }

    // ---- epilogue ----
#pragma unroll
    for (int mi = 0; mi < 2; mi++) {
        int r0 = mbase + m0 + mi * 16 + (lane >> 2);
#pragma unroll
        for (int nf = 0; nf < NF; nf++) {
            int col = n0 + nf * 8 + 2 * (lane & 3);
            if (r0 < n) {
                float2 v; v.x = acc[mi][nf][0]; v.y = acc[mi][nf][1];
                *(float2*)(G + (size_t)r0 * NC + col) = v;
            }
            if (r0 + 8 < n) {
                float2 v; v.x = acc[mi][nf][2]; v.y = acc[mi][nf][3];
                *(float2*)(G + (size_t)(r0 + 8) * NC + col) = v;
            }
        }
    }
}

// -------- aggregation: OUT[i] = act(dinv[i]*(sum_j dinv[j]*G[j] + dinv[i]*G[i]) + bias)
template <int NC, bool RELU>
__global__ __launch_bounds__(256) void k_agg(
    const float* __restrict__ G, const float* __restrict__ bias,
    float* __restrict__ OUT, int n)
{
    constexpr int V = NC / 32;
    int gw = (blockIdx.x * blockDim.x + threadIdx.x) >> 5;
    int lane = threadIdx.x & 31;
    if (gw >= n) return;

    float di = g_dinv[gw];

    float acc[V];
    const float* pself = G + (size_t)gw * NC + lane * V;
    if constexpr (V == 4) {
        float4 v = *(const float4*)pself;
        acc[0] = di * v.x; acc[1] = di * v.y; acc[2] = di * v.z; acc[3] = di * v.w;
    } else {
        float2 v = *(const float2*)pself;
        acc[0] = di * v.x; acc[1] = di * v.y;
    }

    int s = g_rptr[gw], e = g_rptr[gw + 1];
    for (int base = s; base < e; base += 32) {
        int idx = base + lane;
        int sj = 0;
        float dj = 0.0f;
        if (idx < e) {
            sj = g_csr[idx];
            dj = g_dinv[sj];
        }
        int m = e - base; if (m > 32) m = 32;
        int j = 0;
        for (; j + 4 <= m; j += 4) {
            int s0 = __shfl_sync(0xffffffffu, sj, j);
            int s1 = __shfl_sync(0xffffffffu, sj, j + 1);
            int s2 = __shfl_sync(0xffffffffu, sj, j + 2);
            int s3 = __shfl_sync(0xffffffffu, sj, j + 3);
            float d0 = __shfl_sync(0xffffffffu, dj, j);
            float d1 = __shfl_sync(0xffffffffu, dj, j + 1);
            float d2 = __shfl_sync(0xffffffffu, dj, j + 2);
            float d3 = __shfl_sync(0xffffffffu, dj, j + 3);
            if constexpr (V == 4) {
                float4 a = *(const float4*)(G + (size_t)s0 * NC + lane * 4);
                float4 b = *(const float4*)(G + (size_t)s1 * NC + lane * 4);
                float4 c = *(const float4*)(G + (size_t)s2 * NC + lane * 4);
                float4 d = *(const float4*)(G + (size_t)s3 * NC + lane * 4);
                acc[0] += d0 * a.x + d1 * b.x; acc[1] += d0 * a.y + d1 * b.y;
                acc[2] += d0 * a.z + d1 * b.z; acc[3] += d0 * a.w + d1 * b.w;
                acc[0] += d2 * c.x + d3 * d.x; acc[1] += d2 * c.y + d3 * d.y;
                acc[2] += d2 * c.z + d3 * d.z; acc[3] += d2 * c.w + d3 * d.w;
            } else {
                float2 a = *(const float2*)(G + (size_t)s0 * NC + lane * 2);
                float2 b = *(const float2*)(G + (size_t)s1 * NC + lane * 2);
                float2 c = *(const float2*)(G + (size_t)s2 * NC + lane * 2);
                float2 d = *(const float2*)(G + (size_t)s3 * NC + lane * 2);
                acc[0] += d0 * a.x + d1 * b.x; acc[1] += d0 * a.y + d1 * b.y;
                acc[0] += d2 * c.x + d3 * d.x; acc[1] += d2 * c.y + d3 * d.y;
            }
        }
        for (; j < m; j++) {
            int s0 = __shfl_sync(0xffffffffu, sj, j);
            float d0 = __shfl_sync(0xffffffffu, dj, j);
            const float* p = G + (size_t)s0 * NC + lane * V;
            if constexpr (V == 4) {
                float4 a = *(const float4*)p;
                acc[0] += d0 * a.x; acc[1] += d0 * a.y;
                acc[2] += d0 * a.z; acc[3] += d0 * a.w;
            } else {
                float2 a = *(const float2*)p;
                acc[0] += d0 * a.x; acc[1] += d0 * a.y;
            }
        }
    }

    float bv[V];
    if constexpr (V == 4) {
        float4 b = *(const float4*)(bias + lane * 4);
        bv[0] = b.x; bv[1] = b.y; bv[2] = b.z; bv[3] = b.w;
    } else {
        float2 b = *(const float2*)(bias + lane * 2);
        bv[0] = b.x; bv[1] = b.y;
    }
    float r[V];
#pragma unroll
    for (int v = 0; v < V; v++) {
        r[v] = acc[v] * di + bv[v];
        if (RELU) r[v] = fmaxf(r[v], 0.0f);
    }
    float* po = OUT + (size_t)gw * NC + lane * V;
    if constexpr (V == 4) {
        float4 o; o.x = r[0]; o.y = r[1]; o.z = r[2]; o.w = r[3];
        *(float4*)po = o;
    } else {
        float2 o; o.x = r[0]; o.y = r[1];
        *(float2*)po = o;
    }
}

// ---------------- launch ----------------
extern "C" void kernel_launch(void* const* d_in, const int* in_sizes, int n_in,
                              void* d_out, int out_size)
{
    const float* x  = (const float*)d_in[0];
    const void*  ei = d_in[1];
    const float* W1 = (const float*)d_in[2];
    const float* b1 = (const float*)d_in[3];
    const float* W2 = (const float*)d_in[4];
    const float* b2 = (const float*)d_in[5];
    float* out = (float*)d_out;

    int n = in_sizes[0] / IN_DIM;
    int E = in_sizes[1] / 2;

    float *g1p, *h1p, *g2p;
    cudaGetSymbolAddress((void**)&g1p, g_g1);
    cudaGetSymbolAddress((void**)&h1p, g_h1);
    cudaGetSymbolAddress((void**)&g2p, g_g2);
    __nv_bfloat16 *w1s, *w2s;
    cudaGetSymbolAddress((void**)&w1s, g_w1s);
    cudaGetSymbolAddress((void**)&w2s, g_w2s);

    // smem: A hi/lo (2*64*272) + B hi/lo (2*NC*272)
    const int smem1 = 2 * 64 * 272 + 2 * 128 * 272;   // 104448 -> 2 CTAs/SM
    const int smem2 = 2 * 64 * 272 + 2 * 64 * 272;    //  69632 -> 3 CTAs/SM
    cudaFuncSetAttribute(k_gemm_mma<HID_DIM>, cudaFuncAttributeMaxDynamicSharedMemorySize, smem1);
    cudaFuncSetAttribute(k_gemm_mma<OUT_DIM>, cudaFuncAttributeMaxDynamicSharedMemorySize, smem2);

    int nb1024 = (n + 1023) / 1024;
    int ngrid = (n + 63) / 64;
    int wgrid = (HID_DIM * IN_DIM + OUT_DIM * HID_DIM + 255) / 256;

    k_detect<<<1, 1>>>(ei);                                     // 0
    k_zero<<<(n + 255) / 256, 256>>>(n);                        // 1
    k_prepw<<<wgrid, 256>>>(W1, W2);                            // 2
    k_gemm_mma<HID_DIM><<<ngrid, 256, smem1>>>(x, w1s, g1p, n); // 3 (ncu slot)

    k_convcnt<<<(E + 255) / 256, 256>>>(ei, E);
    k_scanA<<<nb1024, 1024>>>(n);
    k_scanB<<<1, 32>>>(nb1024);
    k_scanC<<<(n + 255) / 256, 256>>>(n, E);
    k_scatter<<<(E + 255) / 256, 256>>>(E);

    k_agg<HID_DIM, true><<<(n * 32 + 255) / 256, 256>>>(g1p, b1, h1p, n);
    k_gemm_mma<OUT_DIM><<<ngrid, 256, smem2>>>(h1p, w2s, g2p, n);
    k_agg<OUT_DIM, false><<<(n * 32 + 255) / 256, 256>>>(g2p, b2, out, n);
}

// round 8
// speedup vs baseline: 1.3949x; 1.0423x over previous
#include <cuda_runtime.h>
#include <cuda_bf16.h>
#include <cstdint>

// ---------------- problem constants ----------------
#define N_MAX 100000
#define E_MAX 1600000
#define IN_DIM 128
#define HID_DIM 128
#define OUT_DIM 64

typedef unsigned long long u64;

// ---------------- device scratch ----------------
__device__ int   g_is64;
__device__ int   g_esrc[E_MAX];
__device__ int   g_edst[E_MAX];
__device__ int   g_cnt[N_MAX];
__device__ int   g_rptr[N_MAX + 1];
__device__ int   g_cursor[N_MAX];
__device__ int   g_part[256];
__device__ float g_dinv[N_MAX];
__device__ int   g_csr[E_MAX];
__device__ __align__(16) float g_g1[(size_t)N_MAX * HID_DIM];
__device__ __align__(16) float g_h1[(size_t)N_MAX * HID_DIM];
__device__ __align__(16) float g_g2[(size_t)N_MAX * OUT_DIM];
// pre-split weights, layout Wt[c][k] (k contiguous), hi block then lo block
__device__ __align__(16) __nv_bfloat16 g_w1s[2 * HID_DIM * IN_DIM];
__device__ __align__(16) __nv_bfloat16 g_w2s[2 * OUT_DIM * HID_DIM];

// ---------------- PTX helpers (baseline ISA: ldmatrix + mma.sync) ----------
__device__ __forceinline__ uint32_t smem_u32(const void* p) {
    uint32_t a;
    asm("{ .reg .u64 t; cvta.to.shared.u64 t, %1; cvt.u32.u64 %0, t; }" : "=r"(a) : "l"(p));
    return a;
}
__device__ __forceinline__ void ldsm4(uint32_t* r, uint32_t addr) {
    asm volatile("ldmatrix.sync.aligned.m8n8.x4.shared.b16 {%0,%1,%2,%3}, [%4];"
                 : "=r"(r[0]), "=r"(r[1]), "=r"(r[2]), "=r"(r[3]) : "r"(addr));
}
__device__ __forceinline__ void mma_bf16(float* c, const uint32_t* a, const uint32_t* b) {
    asm volatile(
        "mma.sync.aligned.m16n8k16.row.col.f32.bf16.bf16.f32 "
        "{%0,%1,%2,%3}, {%4,%5,%6,%7}, {%8,%9}, {%0,%1,%2,%3};"
        : "+f"(c[0]), "+f"(c[1]), "+f"(c[2]), "+f"(c[3])
        : "r"(a[0]), "r"(a[1]), "r"(a[2]), "r"(a[3]), "r"(b[0]), "r"(b[1]));
}
__device__ __forceinline__ uint32_t pack2(__nv_bfloat16 a, __nv_bfloat16 b) {
    return (uint32_t)__bfloat16_as_ushort(a) | ((uint32_t)__bfloat16_as_ushort(b) << 16);
}

// ---------------- dtype detection ----------------
__global__ void k_detect(const void* p) {
    const long long* q = (const long long*)p;
    int ok = 1;
    for (int i = 0; i < 8; i++) {
        long long v = q[i];
        if (v < 0 || v >= (long long)N_MAX * 4) ok = 0;
    }
    g_is64 = ok;
}

// ---------------- fused init: zero counters + pre-split both weights -------
__global__ void k_init(const float* __restrict__ W1, const float* __restrict__ W2, int n) {
    int i = blockIdx.x * blockDim.x + threadIdx.x;
    if (i < n) g_cnt[i] = 0;
    if (i < HID_DIM * IN_DIM) {
        int c = i >> 7, k = i & 127;
        float w = W1[(size_t)k * HID_DIM + c];
        __nv_bfloat16 h = __float2bfloat16_rn(w);
        __nv_bfloat16 l = __float2bfloat16_rn(w - __bfloat162float(h));
        g_w1s[c * IN_DIM + k] = h;
        g_w1s[HID_DIM * IN_DIM + c * IN_DIM + k] = l;
    } else if (i < HID_DIM * IN_DIM + OUT_DIM * HID_DIM) {
        int j = i - HID_DIM * IN_DIM;
        int c = j >> 7, k = j & 127;
        float w = W2[(size_t)k * OUT_DIM + c];
        __nv_bfloat16 h = __float2bfloat16_rn(w);
        __nv_bfloat16 l = __float2bfloat16_rn(w - __bfloat162float(h));
        g_w2s[c * HID_DIM + k] = h;
        g_w2s[OUT_DIM * HID_DIM + c * HID_DIM + k] = l;
    }
}

// ---------------- convert + count fused ----------------
__global__ void k_convcnt(const void* p, int E) {
    int e = blockIdx.x * blockDim.x + threadIdx.x;
    if (e >= E) return;
    int s, d;
    if (g_is64) {
        const long long* q = (const long long*)p;
        s = (int)q[e];
        d = (int)q[(size_t)E + e];
    } else {
        const int* q = (const int*)p;
        s = q[e];
        d = q[E + e];
    }
    g_esrc[e] = s;
    g_edst[e] = d;
    atomicAdd(&g_cnt[d], 1);
}

// ---------------- scan / scatter ----------------
__global__ void k_scanA(int n) {
    __shared__ int sh[1024];
    int t = threadIdx.x;
    int idx = blockIdx.x * 1024 + t;
    int v = (idx < n) ? g_cnt[idx] : 0;
    sh[t] = v;
    __syncthreads();
#pragma unroll
    for (int off = 1; off < 1024; off <<= 1) {
        int add = (t >= off) ? sh[t - off] : 0;
        __syncthreads();
        sh[t] += add;
        __syncthreads();
    }
    int incl = sh[t];
    if (idx < n) g_rptr[idx] = incl - v;
    if (t == 1023) g_part[blockIdx.x] = incl;
}

// parallel exclusive scan of up to 128 block partials (128 threads)
__global__ void k_scanB(int nb) {
    __shared__ int sh[128];
    int t = threadIdx.x;
    int v = (t < nb) ? g_part[t] : 0;
    sh[t] = v;
    __syncthreads();
#pragma unroll
    for (int off = 1; off < 128; off <<= 1) {
        int add = (t >= off) ? sh[t - off] : 0;
        __syncthreads();
        sh[t] += add;
        __syncthreads();
    }
    if (t < nb) g_part[t] = sh[t] - v;   // exclusive
}

__global__ void k_scanC(int n, int E) {
    int idx = blockIdx.x * blockDim.x + threadIdx.x;
    if (idx < n) {
        int r = g_rptr[idx] + g_part[idx >> 10];
        g_rptr[idx] = r;
        g_cursor[idx] = r;
        g_dinv[idx] = rsqrtf((float)g_cnt[idx] + 1.0f);
    }
    if (idx == 0) g_rptr[n] = E;
}

__global__ void k_scatter(int E) {
    int e = blockIdx.x * blockDim.x + threadIdx.x;
    if (e >= E) return;
    int d = g_edst[e];
    int pos = atomicAdd(&g_cursor[d], 1);
    g_csr[pos] = g_esrc[e];
}

// ---------------- GEMM: G = X @ W via split-bf16 mma.sync ------------------
// Register double-buffered mainloop: prefetch k-step ks+1 LDSMs before the
// MMAs of k-step ks. __launch_bounds__(256,2) keeps 2 CTAs/SM.
template <int NC>
struct Frags {
    uint32_t ah[2][4], al[2][4];
    uint32_t bh[NC / 32][2], bl[NC / 32][2];
};

template <int NC>
__device__ __forceinline__ void load_frags(
    Frags<NC>& f, uint32_t a_addr0, uint32_t b_addr0,
    uint32_t a_lo_off, uint32_t b_lo_off, int ks, int PITCH)
{
    uint32_t koff = ks * 32;
#pragma unroll
    for (int mi = 0; mi < 2; mi++) {
        ldsm4(f.ah[mi], a_addr0 + mi * 16 * PITCH + koff);
        ldsm4(f.al[mi], a_addr0 + a_lo_off + mi * 16 * PITCH + koff);
    }
#pragma unroll
    for (int pr = 0; pr < NC / 64; pr++) {
        uint32_t r[4];
        ldsm4(r, b_addr0 + pr * 16 * PITCH + koff);
        f.bh[2 * pr][0] = r[0]; f.bh[2 * pr][1] = r[1];
        f.bh[2 * pr + 1][0] = r[2]; f.bh[2 * pr + 1][1] = r[3];
        ldsm4(r, b_addr0 + b_lo_off + pr * 16 * PITCH + koff);
        f.bl[2 * pr][0] = r[0]; f.bl[2 * pr][1] = r[1];
        f.bl[2 * pr + 1][0] = r[2]; f.bl[2 * pr + 1][1] = r[3];
    }
}

template <int NC>
__global__ __launch_bounds__(256, 2) void k_gemm_mma(
    const float* __restrict__ X, const __nv_bfloat16* __restrict__ Ws,
    float* __restrict__ G, int n)
{
    extern __shared__ char smem[];
    constexpr int PITCH = 272;
    constexpr int BM = 64;
    constexpr int AH = 0;
    constexpr int AL = AH + BM * PITCH;
    constexpr int BH = AL + BM * PITCH;
    constexpr int BL = BH + NC * PITCH;
    constexpr int NF = NC / 32;

    uint32_t sb = smem_u32(smem);
    int tid = threadIdx.x;
    int mbase = blockIdx.x * BM;

    // ---- A: load X rows (64 x 128 fp32), split to bf16 hi/lo ----
    {
        int r = tid >> 2;
        int k0 = (tid & 3) * 32;
        int row = mbase + r;
        char* ahp = smem + AH + r * PITCH;
        char* alp = smem + AL + r * PITCH;
#pragma unroll
        for (int k = k0; k < k0 + 32; k += 4) {
            float4 v = make_float4(0.f, 0.f, 0.f, 0.f);
            if (row < n) v = *(const float4*)(X + (size_t)row * IN_DIM + k);
            __nv_bfloat16 h0 = __float2bfloat16_rn(v.x);
            __nv_bfloat16 h1 = __float2bfloat16_rn(v.y);
            __nv_bfloat16 h2 = __float2bfloat16_rn(v.z);
            __nv_bfloat16 h3 = __float2bfloat16_rn(v.w);
            __nv_bfloat16 l0 = __float2bfloat16_rn(v.x - __bfloat162float(h0));
            __nv_bfloat16 l1 = __float2bfloat16_rn(v.y - __bfloat162float(h1));
            __nv_bfloat16 l2 = __float2bfloat16_rn(v.z - __bfloat162float(h2));
            __nv_bfloat16 l3 = __float2bfloat16_rn(v.w - __bfloat162float(h3));
            uint2 hv; hv.x = pack2(h0, h1); hv.y = pack2(h2, h3);
            uint2 lv; lv.x = pack2(l0, l1); lv.y = pack2(l2, l3);
            *(uint2*)(ahp + k * 2) = hv;
            *(uint2*)(alp + k * 2) = lv;
        }
    }
    // ---- B: copy pre-split Wt hi/lo ----
    {
        constexpr int BU4 = NC * 128 * 2 / 16;
        const uint4* ws4 = (const uint4*)Ws;
#pragma unroll
        for (int r = 0; r < BU4 / 256; r++) {
            int li = tid + r * 256;
            int c = li >> 4;
            int ch = li & 15;
            *(uint4*)(smem + BH + c * PITCH + ch * 16) = ws4[li];
            *(uint4*)(smem + BL + c * PITCH + ch * 16) = ws4[BU4 + li];
        }
    }
    __syncthreads();

    int wid = tid >> 5;
    int lane = tid & 31;
    int wm = wid & 1;
    int wn = wid >> 1;
    int m0 = wm * 32;
    int n0 = wn * (NC / 4);

    float acc[2][NF][4];
#pragma unroll
    for (int mi = 0; mi < 2; mi++)
#pragma unroll
        for (int nf = 0; nf < NF; nf++)
#pragma unroll
            for (int q = 0; q < 4; q++) acc[mi][nf][q] = 0.0f;

    uint32_t a_addr0 = sb + AH + (uint32_t)(m0 + (lane & 15)) * PITCH + ((lane >> 4) * 16);
    uint32_t b_row   = (uint32_t)(n0 + (lane & 7) + ((lane >> 4) & 1) * 8);
    uint32_t b_addr0 = sb + BH + b_row * PITCH + (((lane >> 3) & 1) * 16);

    Frags<NC> f[2];
    load_frags<NC>(f[0], a_addr0, b_addr0, AL - AH, BL - BH, 0, PITCH);

#pragma unroll
    for (int ks = 0; ks < 8; ks++) {
        if (ks + 1 < 8)
            load_frags<NC>(f[(ks + 1) & 1], a_addr0, b_addr0, AL - AH, BL - BH, ks + 1, PITCH);
        Frags<NC>& c = f[ks & 1];
#pragma unroll
        for (int mi = 0; mi < 2; mi++)
#pragma unroll
            for (int nf = 0; nf < NF; nf++) {
                mma_bf16(acc[mi][nf], c.ah[mi], c.bh[nf]);
                mma_bf16(acc[mi][nf], c.ah[mi], c.bl[nf]);
                mma_bf16(acc[mi][nf], c.al[mi], c.bh[nf]);
            }
    }

    // ---- epilogue ----
#pragma unroll
    for (int mi = 0; mi < 2; mi++) {
        int r0 = mbase + m0 + mi * 16 + (lane >> 2);
#pragma unroll
        for (int nf = 0; nf < NF; nf++) {
            int col = n0 + nf * 8 + 2 * (lane & 3);
            if (r0 < n) {
                float2 v; v.x = acc[mi][nf][0]; v.y = acc[mi][nf][1];
                *(float2*)(G + (size_t)r0 * NC + col) = v;
            }
            if (r0 + 8 < n) {
                float2 v; v.x = acc[mi][nf][2]; v.y = acc[mi][nf][3];
                *(float2*)(G + (size_t)(r0 + 8) * NC + col) = v;
            }
        }
    }
}

// -------- aggregation: OUT[i] = act(dinv[i]*(sum_j dinv[j]*G[j] + dinv[i]*G[i]) + bias)
template <int NC, bool RELU>
__global__ __launch_bounds__(256) void k_agg(
    const float* __restrict__ G, const float* __restrict__ bias,
    float* __restrict__ OUT, int n)
{
    constexpr int V = NC / 32;
    int gw = (blockIdx.x * blockDim.x + threadIdx.x) >> 5;
    int lane = threadIdx.x & 31;
    if (gw >= n) return;

    float di = g_dinv[gw];

    float acc[V];
    const float* pself = G + (size_t)gw * NC + lane * V;
    if constexpr (V == 4) {
        float4 v = *(const float4*)pself;
        acc[0] = di * v.x; acc[1] = di * v.y; acc[2] = di * v.z; acc[3] = di * v.w;
    } else {
        float2 v = *(const float2*)pself;
        acc[0] = di * v.x; acc[1] = di * v.y;
    }

    int s = g_rptr[gw], e = g_rptr[gw + 1];
    for (int base = s; base < e; base += 32) {
        int idx = base + lane;
        int sj = 0;
        float dj = 0.0f;
        if (idx < e) {
            sj = g_csr[idx];
            dj = g_dinv[sj];
        }
        int m = e - base; if (m > 32) m = 32;
        int j = 0;
        for (; j + 4 <= m; j += 4) {
            int s0 = __shfl_sync(0xffffffffu, sj, j);
            int s1 = __shfl_sync(0xffffffffu, sj, j + 1);
            int s2 = __shfl_sync(0xffffffffu, sj, j + 2);
            int s3 = __shfl_sync(0xffffffffu, sj, j + 3);
            float d0 = __shfl_sync(0xffffffffu, dj, j);
            float d1 = __shfl_sync(0xffffffffu, dj, j + 1);
            float d2 = __shfl_sync(0xffffffffu, dj, j + 2);
            float d3 = __shfl_sync(0xffffffffu, dj, j + 3);
            if constexpr (V == 4) {
                float4 a = *(const float4*)(G + (size_t)s0 * NC + lane * 4);
                float4 b = *(const float4*)(G + (size_t)s1 * NC + lane * 4);
                float4 c = *(const float4*)(G + (size_t)s2 * NC + lane * 4);
                float4 d = *(const float4*)(G + (size_t)s3 * NC + lane * 4);
                acc[0] += d0 * a.x + d1 * b.x; acc[1] += d0 * a.y + d1 * b.y;
                acc[2] += d0 * a.z + d1 * b.z; acc[3] += d0 * a.w + d1 * b.w;
                acc[0] += d2 * c.x + d3 * d.x; acc[1] += d2 * c.y + d3 * d.y;
                acc[2] += d2 * c.z + d3 * d.z; acc[3] += d2 * c.w + d3 * d.w;
            } else {
                float2 a = *(const float2*)(G + (size_t)s0 * NC + lane * 2);
                float2 b = *(const float2*)(G + (size_t)s1 * NC + lane * 2);
                float2 c = *(const float2*)(G + (size_t)s2 * NC + lane * 2);
                float2 d = *(const float2*)(G + (size_t)s3 * NC + lane * 2);
                acc[0] += d0 * a.x + d1 * b.x; acc[1] += d0 * a.y + d1 * b.y;
                acc[0] += d2 * c.x + d3 * d.x; acc[1] += d2 * c.y + d3 * d.y;
            }
        }
        for (; j < m; j++) {
            int s0 = __shfl_sync(0xffffffffu, sj, j);
            float d0 = __shfl_sync(0xffffffffu, dj, j);
            const float* p = G + (size_t)s0 * NC + lane * V;
            if constexpr (V == 4) {
                float4 a = *(const float4*)p;
                acc[0] += d0 * a.x; acc[1] += d0 * a.y;
                acc[2] += d0 * a.z; acc[3] += d0 * a.w;
            } else {
                float2 a = *(const float2*)p;
                acc[0] += d0 * a.x; acc[1] += d0 * a.y;
            }
        }
    }

    float bv[V];
    if constexpr (V == 4) {
        float4 b = *(const float4*)(bias + lane * 4);
        bv[0] = b.x; bv[1] = b.y; bv[2] = b.z; bv[3] = b.w;
    } else {
        float2 b = *(const float2*)(bias + lane * 2);
        bv[0] = b.x; bv[1] = b.y;
    }
    float r[V];
#pragma unroll
    for (int v = 0; v < V; v++) {
        r[v] = acc[v] * di + bv[v];
        if (RELU) r[v] = fmaxf(r[v], 0.0f);
    }
    float* po = OUT + (size_t)gw * NC + lane * V;
    if constexpr (V == 4) {
        float4 o; o.x = r[0]; o.y = r[1]; o.z = r[2]; o.w = r[3];
        *(float4*)po = o;
    } else {
        float2 o; o.x = r[0]; o.y = r[1];
        *(float2*)po = o;
    }
}

// ---------------- launch ----------------
extern "C" void kernel_launch(void* const* d_in, const int* in_sizes, int n_in,
                              void* d_out, int out_size)
{
    const float* x  = (const float*)d_in[0];
    const void*  ei = d_in[1];
    const float* W1 = (const float*)d_in[2];
    const float* b1 = (const float*)d_in[3];
    const float* W2 = (const float*)d_in[4];
    const float* b2 = (const float*)d_in[5];
    float* out = (float*)d_out;

    int n = in_sizes[0] / IN_DIM;
    int E = in_sizes[1] / 2;

    float *g1p, *h1p, *g2p;
    cudaGetSymbolAddress((void**)&g1p, g_g1);
    cudaGetSymbolAddress((void**)&h1p, g_h1);
    cudaGetSymbolAddress((void**)&g2p, g_g2);
    __nv_bfloat16 *w1s, *w2s;
    cudaGetSymbolAddress((void**)&w1s, g_w1s);
    cudaGetSymbolAddress((void**)&w2s, g_w2s);

    const int smem1 = 2 * 64 * 272 + 2 * 128 * 272;   // 104448 -> 2 CTAs/SM
    const int smem2 = 2 * 64 * 272 + 2 * 64 * 272;    //  69632
    cudaFuncSetAttribute(k_gemm_mma<HID_DIM>, cudaFuncAttributeMaxDynamicSharedMemorySize, smem1);
    cudaFuncSetAttribute(k_gemm_mma<OUT_DIM>, cudaFuncAttributeMaxDynamicSharedMemorySize, smem2);

    int nb1024 = (n + 1023) / 1024;
    int ngrid = (n + 63) / 64;
    int igrid = (n > HID_DIM * IN_DIM + OUT_DIM * HID_DIM ? n
                 : HID_DIM * IN_DIM + OUT_DIM * HID_DIM);

    k_detect<<<1, 1>>>(ei);                                     // 0
    k_init<<<(igrid + 255) / 256, 256>>>(W1, W2, n);            // 1
    k_convcnt<<<(E + 255) / 256, 256>>>(ei, E);                 // 2
    k_gemm_mma<HID_DIM><<<ngrid, 256, smem1>>>(x, w1s, g1p, n); // 3 (ncu slot)

    k_scanA<<<nb1024, 1024>>>(n);
    k_scanB<<<1, 128>>>(nb1024);
    k_scanC<<<(n + 255) / 256, 256>>>(n, E);
    k_scatter<<<(E + 255) / 256, 256>>>(E);

    k_agg<HID_DIM, true><<<(n * 32 + 255) / 256, 256>>>(g1p, b1, h1p, n);
    k_gemm_mma<OUT_DIM><<<ngrid, 256, smem2>>>(h1p, w2s, g2p, n);
    k_agg<OUT_DIM, false><<<(n * 32 + 255) / 256, 256>>>(g2p, b2, out, n);
}

// round 9
// speedup vs baseline: 1.5927x; 1.1418x over previous
#include <cuda_runtime.h>
#include <cuda_bf16.h>
#include <cuda_fp16.h>
#include <cstdint>

// ---------------- problem constants ----------------
#define N_MAX 100000
#define E_MAX 1600000
#define IN_DIM 128
#define HID_DIM 128
#define OUT_DIM 64

typedef unsigned long long u64;

// ---------------- device scratch ----------------
__device__ int   g_is64;
__device__ int   g_esrc[E_MAX];
__device__ int   g_edst[E_MAX];
__device__ int   g_cnt[N_MAX];
__device__ int   g_rptr[N_MAX + 1];
__device__ int   g_cursor[N_MAX];
__device__ int   g_part[256];
__device__ float g_dinv[N_MAX];
__device__ int   g_csr[E_MAX];
// fp16 message/feature buffers (halved gather traffic)
__device__ __align__(16) __half g_g1[(size_t)N_MAX * HID_DIM];
__device__ __align__(16) __half g_h1[(size_t)N_MAX * HID_DIM];
__device__ __align__(16) __half g_g2[(size_t)N_MAX * OUT_DIM];
// pre-split weights, layout Wt[c][k] (k contiguous), hi block then lo block
__device__ __align__(16) __nv_bfloat16 g_w1s[2 * HID_DIM * IN_DIM];
__device__ __align__(16) __nv_bfloat16 g_w2s[2 * OUT_DIM * HID_DIM];

// ---------------- PTX helpers (baseline ISA: ldmatrix + mma.sync) ----------
__device__ __forceinline__ uint32_t smem_u32(const void* p) {
    uint32_t a;
    asm("{ .reg .u64 t; cvta.to.shared.u64 t, %1; cvt.u32.u64 %0, t; }" : "=r"(a) : "l"(p));
    return a;
}
__device__ __forceinline__ void ldsm4(uint32_t* r, uint32_t addr) {
    asm volatile("ldmatrix.sync.aligned.m8n8.x4.shared.b16 {%0,%1,%2,%3}, [%4];"
                 : "=r"(r[0]), "=r"(r[1]), "=r"(r[2]), "=r"(r[3]) : "r"(addr));
}
__device__ __forceinline__ void mma_bf16(float* c, const uint32_t* a, const uint32_t* b) {
    asm volatile(
        "mma.sync.aligned.m16n8k16.row.col.f32.bf16.bf16.f32 "
        "{%0,%1,%2,%3}, {%4,%5,%6,%7}, {%8,%9}, {%0,%1,%2,%3};"
        : "+f"(c[0]), "+f"(c[1]), "+f"(c[2]), "+f"(c[3])
        : "r"(a[0]), "r"(a[1]), "r"(a[2]), "r"(a[3]), "r"(b[0]), "r"(b[1]));
}
__device__ __forceinline__ uint32_t pack2(__nv_bfloat16 a, __nv_bfloat16 b) {
    return (uint32_t)__bfloat16_as_ushort(a) | ((uint32_t)__bfloat16_as_ushort(b) << 16);
}

// ---------------- dtype detection ----------------
__global__ void k_detect(const void* p) {
    const long long* q = (const long long*)p;
    int ok = 1;
    for (int i = 0; i < 8; i++) {
        long long v = q[i];
        if (v < 0 || v >= (long long)N_MAX * 4) ok = 0;
    }
    g_is64 = ok;
}

// ---------------- fused init: zero counters + pre-split both weights -------
__global__ void k_init(const float* __restrict__ W1, const float* __restrict__ W2, int n) {
    int i = blockIdx.x * blockDim.x + threadIdx.x;
    if (i < n) g_cnt[i] = 0;
    if (i < HID_DIM * IN_DIM) {
        int c = i >> 7, k = i & 127;
        float w = W1[(size_t)k * HID_DIM + c];
        __nv_bfloat16 h = __float2bfloat16_rn(w);
        __nv_bfloat16 l = __float2bfloat16_rn(w - __bfloat162float(h));
        g_w1s[c * IN_DIM + k] = h;
        g_w1s[HID_DIM * IN_DIM + c * IN_DIM + k] = l;
    } else if (i < HID_DIM * IN_DIM + OUT_DIM * HID_DIM) {
        int j = i - HID_DIM * IN_DIM;
        int c = j >> 7, k = j & 127;
        float w = W2[(size_t)k * OUT_DIM + c];
        __nv_bfloat16 h = __float2bfloat16_rn(w);
        __nv_bfloat16 l = __float2bfloat16_rn(w - __bfloat162float(h));
        g_w2s[c * HID_DIM + k] = h;
        g_w2s[OUT_DIM * HID_DIM + c * HID_DIM + k] = l;
    }
}

// ---------------- convert + count fused ----------------
__global__ void k_convcnt(const void* p, int E) {
    int e = blockIdx.x * blockDim.x + threadIdx.x;
    if (e >= E) return;
    int s, d;
    if (g_is64) {
        const long long* q = (const long long*)p;
        s = (int)q[e];
        d = (int)q[(size_t)E + e];
    } else {
        const int* q = (const int*)p;
        s = q[e];
        d = q[E + e];
    }
    g_esrc[e] = s;
    g_edst[e] = d;
    atomicAdd(&g_cnt[d], 1);
}

// ---------------- scan / scatter ----------------
__global__ void k_scanA(int n) {
    __shared__ int sh[1024];
    int t = threadIdx.x;
    int idx = blockIdx.x * 1024 + t;
    int v = (idx < n) ? g_cnt[idx] : 0;
    sh[t] = v;
    __syncthreads();
#pragma unroll
    for (int off = 1; off < 1024; off <<= 1) {
        int add = (t >= off) ? sh[t - off] : 0;
        __syncthreads();
        sh[t] += add;
        __syncthreads();
    }
    int incl = sh[t];
    if (idx < n) g_rptr[idx] = incl - v;
    if (t == 1023) g_part[blockIdx.x] = incl;
}

__global__ void k_scanB(int nb) {
    __shared__ int sh[128];
    int t = threadIdx.x;
    int v = (t < nb) ? g_part[t] : 0;
    sh[t] = v;
    __syncthreads();
#pragma unroll
    for (int off = 1; off < 128; off <<= 1) {
        int add = (t >= off) ? sh[t - off] : 0;
        __syncthreads();
        sh[t] += add;
        __syncthreads();
    }
    if (t < nb) g_part[t] = sh[t] - v;   // exclusive
}

__global__ void k_scanC(int n, int E) {
    int idx = blockIdx.x * blockDim.x + threadIdx.x;
    if (idx < n) {
        int r = g_rptr[idx] + g_part[idx >> 10];
        g_rptr[idx] = r;
        g_cursor[idx] = r;
        g_dinv[idx] = rsqrtf((float)g_cnt[idx] + 1.0f);
    }
    if (idx == 0) g_rptr[n] = E;
}

__global__ void k_scatter(int E) {
    int e = blockIdx.x * blockDim.x + threadIdx.x;
    if (e >= E) return;
    int d = g_edst[e];
    int pos = atomicAdd(&g_cursor[d], 1);
    g_csr[pos] = g_esrc[e];
}

// ---------------- GEMM: G(fp16) = X @ W via split-bf16 mma.sync ------------
template <int NC>
struct Frags {
    uint32_t ah[2][4], al[2][4];
    uint32_t bh[NC / 32][2], bl[NC / 32][2];
};

template <int NC>
__device__ __forceinline__ void load_frags(
    Frags<NC>& f, uint32_t a_addr0, uint32_t b_addr0,
    uint32_t a_lo_off, uint32_t b_lo_off, int ks, int PITCH)
{
    uint32_t koff = ks * 32;
#pragma unroll
    for (int mi = 0; mi < 2; mi++) {
        ldsm4(f.ah[mi], a_addr0 + mi * 16 * PITCH + koff);
        ldsm4(f.al[mi], a_addr0 + a_lo_off + mi * 16 * PITCH + koff);
    }
#pragma unroll
    for (int pr = 0; pr < NC / 64; pr++) {
        uint32_t r[4];
        ldsm4(r, b_addr0 + pr * 16 * PITCH + koff);
        f.bh[2 * pr][0] = r[0]; f.bh[2 * pr][1] = r[1];
        f.bh[2 * pr + 1][0] = r[2]; f.bh[2 * pr + 1][1] = r[3];
        ldsm4(r, b_addr0 + b_lo_off + pr * 16 * PITCH + koff);
        f.bl[2 * pr][0] = r[0]; f.bl[2 * pr][1] = r[1];
        f.bl[2 * pr + 1][0] = r[2]; f.bl[2 * pr + 1][1] = r[3];
    }
}

// TIn = float (layer 1) or __half (layer 2; fp16->bf16 split is exact)
template <int NC, typename TIn>
__global__ __launch_bounds__(256, 2) void k_gemm_mma(
    const TIn* __restrict__ X, const __nv_bfloat16* __restrict__ Ws,
    __half* __restrict__ G, int n)
{
    extern __shared__ char smem[];
    constexpr int PITCH = 272;
    constexpr int BM = 64;
    constexpr int AH = 0;
    constexpr int AL = AH + BM * PITCH;
    constexpr int BH = AL + BM * PITCH;
    constexpr int BL = BH + NC * PITCH;
    constexpr int NF = NC / 32;

    uint32_t sb = smem_u32(smem);
    int tid = threadIdx.x;
    int mbase = blockIdx.x * BM;

    // ---- A: load X rows (64 x 128), split to bf16 hi/lo ----
    {
        int r = tid >> 2;
        int k0 = (tid & 3) * 32;
        int row = mbase + r;
        char* ahp = smem + AH + r * PITCH;
        char* alp = smem + AL + r * PITCH;
#pragma unroll
        for (int k = k0; k < k0 + 32; k += 4) {
            float vv[4];
            if (row < n) {
                if constexpr (sizeof(TIn) == 4) {
                    float4 v = *(const float4*)((const float*)X + (size_t)row * IN_DIM + k);
                    vv[0] = v.x; vv[1] = v.y; vv[2] = v.z; vv[3] = v.w;
                } else {
                    uint2 u = *(const uint2*)((const __half*)X + (size_t)row * IN_DIM + k);
                    __half2 p0 = *(__half2*)&u.x;
                    __half2 p1 = *(__half2*)&u.y;
                    float2 f0 = __half22float2(p0);
                    float2 f1 = __half22float2(p1);
                    vv[0] = f0.x; vv[1] = f0.y; vv[2] = f1.x; vv[3] = f1.y;
                }
            } else {
                vv[0] = vv[1] = vv[2] = vv[3] = 0.0f;
            }
            __nv_bfloat16 h0 = __float2bfloat16_rn(vv[0]);
            __nv_bfloat16 h1 = __float2bfloat16_rn(vv[1]);
            __nv_bfloat16 h2 = __float2bfloat16_rn(vv[2]);
            __nv_bfloat16 h3 = __float2bfloat16_rn(vv[3]);
            __nv_bfloat16 l0 = __float2bfloat16_rn(vv[0] - __bfloat162float(h0));
            __nv_bfloat16 l1 = __float2bfloat16_rn(vv[1] - __bfloat162float(h1));
            __nv_bfloat16 l2 = __float2bfloat16_rn(vv[2] - __bfloat162float(h2));
            __nv_bfloat16 l3 = __float2bfloat16_rn(vv[3] - __bfloat162float(h3));
            uint2 hv; hv.x = pack2(h0, h1); hv.y = pack2(h2, h3);
            uint2 lv; lv.x = pack2(l0, l1); lv.y = pack2(l2, l3);
            *(uint2*)(ahp + k * 2) = hv;
            *(uint2*)(alp + k * 2) = lv;
        }
    }
    // ---- B: copy pre-split Wt hi/lo ----
    {
        constexpr int BU4 = NC * 128 * 2 / 16;
        const uint4* ws4 = (const uint4*)Ws;
#pragma unroll
        for (int r = 0; r < BU4 / 256; r++) {
            int li = tid + r * 256;
            int c = li >> 4;
            int ch = li & 15;
            *(uint4*)(smem + BH + c * PITCH + ch * 16) = ws4[li];
            *(uint4*)(smem + BL + c * PITCH + ch * 16) = ws4[BU4 + li];
        }
    }
    __syncthreads();

    int wid = tid >> 5;
    int lane = tid & 31;
    int wm = wid & 1;
    int wn = wid >> 1;
    int m0 = wm * 32;
    int n0 = wn * (NC / 4);

    float acc[2][NF][4];
#pragma unroll
    for (int mi = 0; mi < 2; mi++)
#pragma unroll
        for (int nf = 0; nf < NF; nf++)
#pragma unroll
            for (int q = 0; q < 4; q++) acc[mi][nf][q] = 0.0f;

    uint32_t a_addr0 = sb + AH + (uint32_t)(m0 + (lane & 15)) * PITCH + ((lane >> 4) * 16);
    uint32_t b_row   = (uint32_t)(n0 + (lane & 7) + ((lane >> 4) & 1) * 8);
    uint32_t b_addr0 = sb + BH + b_row * PITCH + (((lane >> 3) & 1) * 16);

    Frags<NC> f[2];
    load_frags<NC>(f[0], a_addr0, b_addr0, AL - AH, BL - BH, 0, PITCH);

#pragma unroll
    for (int ks = 0; ks < 8; ks++) {
        if (ks + 1 < 8)
            load_frags<NC>(f[(ks + 1) & 1], a_addr0, b_addr0, AL - AH, BL - BH, ks + 1, PITCH);
        Frags<NC>& c = f[ks & 1];
#pragma unroll
        for (int mi = 0; mi < 2; mi++)
#pragma unroll
            for (int nf = 0; nf < NF; nf++) {
                mma_bf16(acc[mi][nf], c.ah[mi], c.bh[nf]);
                mma_bf16(acc[mi][nf], c.ah[mi], c.bl[nf]);
                mma_bf16(acc[mi][nf], c.al[mi], c.bh[nf]);
            }
    }

    // ---- epilogue: fp16 stores (half write traffic) ----
#pragma unroll
    for (int mi = 0; mi < 2; mi++) {
        int r0 = mbase + m0 + mi * 16 + (lane >> 2);
#pragma unroll
        for (int nf = 0; nf < NF; nf++) {
            int col = n0 + nf * 8 + 2 * (lane & 3);
            if (r0 < n) {
                __half2 v = __floats2half2_rn(acc[mi][nf][0], acc[mi][nf][1]);
                *(__half2*)(G + (size_t)r0 * NC + col) = v;
            }
            if (r0 + 8 < n) {
                __half2 v = __floats2half2_rn(acc[mi][nf][2], acc[mi][nf][3]);
                *(__half2*)(G + (size_t)(r0 + 8) * NC + col) = v;
            }
        }
    }
}

// -------- aggregation: OUT[i] = act(dinv[i]*(sum_j dinv[j]*G[j] + dinv[i]*G[i]) + bias)
// G is fp16; accumulate fp32; OutT = __half (layer 1) or float (final output).
template <int NC, bool RELU, typename OutT>
__global__ __launch_bounds__(256) void k_agg(
    const __half* __restrict__ G, const float* __restrict__ bias,
    OutT* __restrict__ OUT, int n)
{
    constexpr int V = NC / 32;            // halfs per lane (4 or 2)
    constexpr int V2 = V / 2;             // half2 per lane (2 or 1)
    int gw = (blockIdx.x * blockDim.x + threadIdx.x) >> 5;
    int lane = threadIdx.x & 31;
    if (gw >= n) return;

    float di = g_dinv[gw];

    float acc[V];
    {
        const __half2* ps = (const __half2*)(G + (size_t)gw * NC + lane * V);
#pragma unroll
        for (int q = 0; q < V2; q++) {
            float2 fv = __half22float2(ps[q]);
            acc[2 * q] = di * fv.x;
            acc[2 * q + 1] = di * fv.y;
        }
    }

    int s = g_rptr[gw], e = g_rptr[gw + 1];
    for (int base = s; base < e; base += 32) {
        int idx = base + lane;
        int sj = 0;
        float dj = 0.0f;
        if (idx < e) {
            sj = g_csr[idx];
            dj = g_dinv[sj];
        }
        int m = e - base; if (m > 32) m = 32;
        int j = 0;
        for (; j + 4 <= m; j += 4) {
            int s0 = __shfl_sync(0xffffffffu, sj, j);
            int s1 = __shfl_sync(0xffffffffu, sj, j + 1);
            int s2 = __shfl_sync(0xffffffffu, sj, j + 2);
            int s3 = __shfl_sync(0xffffffffu, sj, j + 3);
            float d0 = __shfl_sync(0xffffffffu, dj, j);
            float d1 = __shfl_sync(0xffffffffu, dj, j + 1);
            float d2 = __shfl_sync(0xffffffffu, dj, j + 2);
            float d3 = __shfl_sync(0xffffffffu, dj, j + 3);
            const __half2* p0 = (const __half2*)(G + (size_t)s0 * NC + lane * V);
            const __half2* p1 = (const __half2*)(G + (size_t)s1 * NC + lane * V);
            const __half2* p2 = (const __half2*)(G + (size_t)s2 * NC + lane * V);
            const __half2* p3 = (const __half2*)(G + (size_t)s3 * NC + lane * V);
#pragma unroll
            for (int q = 0; q < V2; q++) {
                float2 a = __half22float2(p0[q]);
                float2 b = __half22float2(p1[q]);
                float2 c = __half22float2(p2[q]);
                float2 d = __half22float2(p3[q]);
                acc[2 * q]     += d0 * a.x + d1 * b.x + d2 * c.x + d3 * d.x;
                acc[2 * q + 1] += d0 * a.y + d1 * b.y + d2 * c.y + d3 * d.y;
            }
        }
        for (; j < m; j++) {
            int s0 = __shfl_sync(0xffffffffu, sj, j);
            float d0 = __shfl_sync(0xffffffffu, dj, j);
            const __half2* p = (const __half2*)(G + (size_t)s0 * NC + lane * V);
#pragma unroll
            for (int q = 0; q < V2; q++) {
                float2 a = __half22float2(p[q]);
                acc[2 * q]     += d0 * a.x;
                acc[2 * q + 1] += d0 * a.y;
            }
        }
    }

    float bv[V];
#pragma unroll
    for (int q = 0; q < V2; q++) {
        float2 b = *(const float2*)(bias + lane * V + 2 * q);
        bv[2 * q] = b.x; bv[2 * q + 1] = b.y;
    }
    float r[V];
#pragma unroll
    for (int v = 0; v < V; v++) {
        r[v] = acc[v] * di + bv[v];
        if (RELU) r[v] = fmaxf(r[v], 0.0f);
    }
    if constexpr (sizeof(OutT) == 2) {
        __half2* po = (__half2*)((__half*)OUT + (size_t)gw * NC + lane * V);
#pragma unroll
        for (int q = 0; q < V2; q++)
            po[q] = __floats2half2_rn(r[2 * q], r[2 * q + 1]);
    } else {
        float* po = (float*)OUT + (size_t)gw * NC + lane * V;
#pragma unroll
        for (int q = 0; q < V2; q++) {
            float2 o; o.x = r[2 * q]; o.y = r[2 * q + 1];
            *(float2*)(po + 2 * q) = o;
        }
    }
}

// ---------------- launch ----------------
extern "C" void kernel_launch(void* const* d_in, const int* in_sizes, int n_in,
                              void* d_out, int out_size)
{
    const float* x  = (const float*)d_in[0];
    const void*  ei = d_in[1];
    const float* W1 = (const float*)d_in[2];
    const float* b1 = (const float*)d_in[3];
    const float* W2 = (const float*)d_in[4];
    const float* b2 = (const float*)d_in[5];
    float* out = (float*)d_out;

    int n = in_sizes[0] / IN_DIM;
    int E = in_sizes[1] / 2;

    __half *g1p, *h1p, *g2p;
    cudaGetSymbolAddress((void**)&g1p, g_g1);
    cudaGetSymbolAddress((void**)&h1p, g_h1);
    cudaGetSymbolAddress((void**)&g2p, g_g2);
    __nv_bfloat16 *w1s, *w2s;
    cudaGetSymbolAddress((void**)&w1s, g_w1s);
    cudaGetSymbolAddress((void**)&w2s, g_w2s);

    const int smem1 = 2 * 64 * 272 + 2 * 128 * 272;   // 104448 -> 2 CTAs/SM
    const int smem2 = 2 * 64 * 272 + 2 * 64 * 272;    //  69632
    cudaFuncSetAttribute((const void*)k_gemm_mma<HID_DIM, float>,
                         cudaFuncAttributeMaxDynamicSharedMemorySize, smem1);
    cudaFuncSetAttribute((const void*)k_gemm_mma<OUT_DIM, __half>,
                         cudaFuncAttributeMaxDynamicSharedMemorySize, smem2);

    int nb1024 = (n + 1023) / 1024;
    int ngrid = (n + 63) / 64;
    int igrid = (n > HID_DIM * IN_DIM + OUT_DIM * HID_DIM ? n
                 : HID_DIM * IN_DIM + OUT_DIM * HID_DIM);

    k_detect<<<1, 1>>>(ei);                                            // 0
    k_init<<<(igrid + 255) / 256, 256>>>(W1, W2, n);                   // 1
    k_convcnt<<<(E + 255) / 256, 256>>>(ei, E);                        // 2
    k_gemm_mma<HID_DIM, float><<<ngrid, 256, smem1>>>(x, w1s, g1p, n); // 3 (ncu slot)

    k_scanA<<<nb1024, 1024>>>(n);
    k_scanB<<<1, 128>>>(nb1024);
    k_scanC<<<(n + 255) / 256, 256>>>(n, E);
    k_scatter<<<(E + 255) / 256, 256>>>(E);

    k_agg<HID_DIM, true, __half><<<(n * 32 + 255) / 256, 256>>>(g1p, b1, h1p, n);
    k_gemm_mma<OUT_DIM, __half><<<ngrid, 256, smem2>>>(h1p, w2s, g2p, n);
    k_agg<OUT_DIM, false, float><<<(n * 32 + 255) / 256, 256>>>(g2p, b2, out, n);
}

// round 10
// speedup vs baseline: 1.6219x; 1.0183x over previous
#include <cuda_runtime.h>
#include <cuda_bf16.h>
#include <cuda_fp16.h>
#include <cstdint>

// ---------------- problem constants ----------------
#define N_MAX 100000
#define E_MAX 1600000
#define IN_DIM 128
#define HID_DIM 128
#define OUT_DIM 64

typedef unsigned long long u64;

// ---------------- device scratch ----------------
__device__ int   g_is64;
__device__ int   g_esrc[E_MAX];
__device__ int   g_edst[E_MAX];
__device__ int   g_cnt[N_MAX];
__device__ int   g_rptr[N_MAX + 1];
__device__ int   g_cursor[N_MAX];
__device__ int   g_part[256];
__device__ float g_dinv[N_MAX];
__device__ int   g_csr[E_MAX];
// fp16 message/feature buffers (halved gather traffic)
__device__ __align__(16) __half g_g1[(size_t)N_MAX * HID_DIM];
__device__ __align__(16) __half g_h1[(size_t)N_MAX * HID_DIM];
__device__ __align__(16) __half g_g2[(size_t)N_MAX * OUT_DIM];
// pre-split weights, layout Wt[c][k] (k contiguous), hi block then lo block
__device__ __align__(16) __nv_bfloat16 g_w1s[2 * HID_DIM * IN_DIM];
__device__ __align__(16) __nv_bfloat16 g_w2s[2 * OUT_DIM * HID_DIM];

// ---------------- PTX helpers (baseline ISA: ldmatrix + mma.sync) ----------
__device__ __forceinline__ uint32_t smem_u32(const void* p) {
    uint32_t a;
    asm("{ .reg .u64 t; cvta.to.shared.u64 t, %1; cvt.u32.u64 %0, t; }" : "=r"(a) : "l"(p));
    return a;
}
__device__ __forceinline__ void ldsm4(uint32_t* r, uint32_t addr) {
    asm volatile("ldmatrix.sync.aligned.m8n8.x4.shared.b16 {%0,%1,%2,%3}, [%4];"
                 : "=r"(r[0]), "=r"(r[1]), "=r"(r[2]), "=r"(r[3]) : "r"(addr));
}
__device__ __forceinline__ void mma_bf16(float* c, const uint32_t* a, const uint32_t* b) {
    asm volatile(
        "mma.sync.aligned.m16n8k16.row.col.f32.bf16.bf16.f32 "
        "{%0,%1,%2,%3}, {%4,%5,%6,%7}, {%8,%9}, {%0,%1,%2,%3};"
        : "+f"(c[0]), "+f"(c[1]), "+f"(c[2]), "+f"(c[3])
        : "r"(a[0]), "r"(a[1]), "r"(a[2]), "r"(a[3]), "r"(b[0]), "r"(b[1]));
}
__device__ __forceinline__ uint32_t pack2(__nv_bfloat16 a, __nv_bfloat16 b) {
    return (uint32_t)__bfloat16_as_ushort(a) | ((uint32_t)__bfloat16_as_ushort(b) << 16);
}

// ---------------- dtype detection ----------------
__global__ void k_detect(const void* p) {
    const long long* q = (const long long*)p;
    int ok = 1;
    for (int i = 0; i < 8; i++) {
        long long v = q[i];
        if (v < 0 || v >= (long long)N_MAX * 4) ok = 0;
    }
    g_is64 = ok;
}

// ---------------- fused init: zero counters + pre-split both weights -------
__global__ void k_init(const float* __restrict__ W1, const float* __restrict__ W2, int n) {
    int i = blockIdx.x * blockDim.x + threadIdx.x;
    if (i < n) g_cnt[i] = 0;
    if (i < HID_DIM * IN_DIM) {
        int c = i >> 7, k = i & 127;
        float w = W1[(size_t)k * HID_DIM + c];
        __nv_bfloat16 h = __float2bfloat16_rn(w);
        __nv_bfloat16 l = __float2bfloat16_rn(w - __bfloat162float(h));
        g_w1s[c * IN_DIM + k] = h;
        g_w1s[HID_DIM * IN_DIM + c * IN_DIM + k] = l;
    } else if (i < HID_DIM * IN_DIM + OUT_DIM * HID_DIM) {
        int j = i - HID_DIM * IN_DIM;
        int c = j >> 7, k = j & 127;
        float w = W2[(size_t)k * OUT_DIM + c];
        __nv_bfloat16 h = __float2bfloat16_rn(w);
        __nv_bfloat16 l = __float2bfloat16_rn(w - __bfloat162float(h));
        g_w2s[c * HID_DIM + k] = h;
        g_w2s[OUT_DIM * HID_DIM + c * HID_DIM + k] = l;
    }
}

// ---------------- convert + count fused ----------------
__global__ void k_convcnt(const void* p, int E) {
    int e = blockIdx.x * blockDim.x + threadIdx.x;
    if (e >= E) return;
    int s, d;
    if (g_is64) {
        const long long* q = (const long long*)p;
        s = (int)q[e];
        d = (int)q[(size_t)E + e];
    } else {
        const int* q = (const int*)p;
        s = q[e];
        d = q[E + e];
    }
    g_esrc[e] = s;
    g_edst[e] = d;
    atomicAdd(&g_cnt[d], 1);
}

// ---------------- scan / scatter ----------------
__global__ void k_scanA(int n) {
    __shared__ int sh[1024];
    int t = threadIdx.x;
    int idx = blockIdx.x * 1024 + t;
    int v = (idx < n) ? g_cnt[idx] : 0;
    sh[t] = v;
    __syncthreads();
#pragma unroll
    for (int off = 1; off < 1024; off <<= 1) {
        int add = (t >= off) ? sh[t - off] : 0;
        __syncthreads();
        sh[t] += add;
        __syncthreads();
    }
    int incl = sh[t];
    if (idx < n) g_rptr[idx] = incl - v;
    if (t == 1023) g_part[blockIdx.x] = incl;
}

__global__ void k_scanB(int nb) {
    __shared__ int sh[128];
    int t = threadIdx.x;
    int v = (t < nb) ? g_part[t] : 0;
    sh[t] = v;
    __syncthreads();
#pragma unroll
    for (int off = 1; off < 128; off <<= 1) {
        int add = (t >= off) ? sh[t - off] : 0;
        __syncthreads();
        sh[t] += add;
        __syncthreads();
    }
    if (t < nb) g_part[t] = sh[t] - v;   // exclusive
}

__global__ void k_scanC(int n, int E) {
    int idx = blockIdx.x * blockDim.x + threadIdx.x;
    if (idx < n) {
        int r = g_rptr[idx] + g_part[idx >> 10];
        g_rptr[idx] = r;
        g_cursor[idx] = r;
        g_dinv[idx] = rsqrtf((float)g_cnt[idx] + 1.0f);
    }
    if (idx == 0) g_rptr[n] = E;
}

__global__ void k_scatter(int E) {
    int e = blockIdx.x * blockDim.x + threadIdx.x;
    if (e >= E) return;
    int d = g_edst[e];
    int pos = atomicAdd(&g_cursor[d], 1);
    g_csr[pos] = g_esrc[e];
}

// ---------------- persistent GEMM: G(fp16) = X @ W, split-bf16 mma.sync ----
// 296 CTAs (2/SM). Each CTA loads B ONCE into smem, then grid-strides over
// M-tiles (64 rows each): load/split A, sync, mainloop, epilogue, sync.
template <int NC>
struct Frags {
    uint32_t ah[2][4], al[2][4];
    uint32_t bh[NC / 32][2], bl[NC / 32][2];
};

template <int NC>
__device__ __forceinline__ void load_frags(
    Frags<NC>& f, uint32_t a_addr0, uint32_t b_addr0,
    uint32_t a_lo_off, uint32_t b_lo_off, int ks, int PITCH)
{
    uint32_t koff = ks * 32;
#pragma unroll
    for (int mi = 0; mi < 2; mi++) {
        ldsm4(f.ah[mi], a_addr0 + mi * 16 * PITCH + koff);
        ldsm4(f.al[mi], a_addr0 + a_lo_off + mi * 16 * PITCH + koff);
    }
#pragma unroll
    for (int pr = 0; pr < NC / 64; pr++) {
        uint32_t r[4];
        ldsm4(r, b_addr0 + pr * 16 * PITCH + koff);
        f.bh[2 * pr][0] = r[0]; f.bh[2 * pr][1] = r[1];
        f.bh[2 * pr + 1][0] = r[2]; f.bh[2 * pr + 1][1] = r[3];
        ldsm4(r, b_addr0 + b_lo_off + pr * 16 * PITCH + koff);
        f.bl[2 * pr][0] = r[0]; f.bl[2 * pr][1] = r[1];
        f.bl[2 * pr + 1][0] = r[2]; f.bl[2 * pr + 1][1] = r[3];
    }
}

// TIn = float (layer 1) or __half (layer 2; fp16->bf16 split is exact)
template <int NC, typename TIn>
__global__ __launch_bounds__(256, 2) void k_gemm_mma(
    const TIn* __restrict__ X, const __nv_bfloat16* __restrict__ Ws,
    __half* __restrict__ G, int n, int ntiles)
{
    extern __shared__ char smem[];
    constexpr int PITCH = 272;
    constexpr int BM = 64;
    constexpr int AH = 0;
    constexpr int AL = AH + BM * PITCH;
    constexpr int BH = AL + BM * PITCH;
    constexpr int BL = BH + NC * PITCH;
    constexpr int NF = NC / 32;

    uint32_t sb = smem_u32(smem);
    int tid = threadIdx.x;

    // ---- B: copy pre-split Wt hi/lo ONCE per CTA ----
    {
        constexpr int BU4 = NC * 128 * 2 / 16;
        const uint4* ws4 = (const uint4*)Ws;
#pragma unroll
        for (int r = 0; r < BU4 / 256; r++) {
            int li = tid + r * 256;
            int c = li >> 4;
            int ch = li & 15;
            *(uint4*)(smem + BH + c * PITCH + ch * 16) = ws4[li];
            *(uint4*)(smem + BL + c * PITCH + ch * 16) = ws4[BU4 + li];
        }
    }

    int wid = tid >> 5;
    int lane = tid & 31;
    int wm = wid & 1;
    int wn = wid >> 1;
    int m0 = wm * 32;
    int n0 = wn * (NC / 4);

    uint32_t a_addr0 = sb + AH + (uint32_t)(m0 + (lane & 15)) * PITCH + ((lane >> 4) * 16);
    uint32_t b_row   = (uint32_t)(n0 + (lane & 7) + ((lane >> 4) & 1) * 8);
    uint32_t b_addr0 = sb + BH + b_row * PITCH + (((lane >> 3) & 1) * 16);

    // A-prologue thread mapping
    int ar = tid >> 2;                 // 0..63
    int ak0 = (tid & 3) * 32;
    char* ahp = smem + AH + ar * PITCH;
    char* alp = smem + AL + ar * PITCH;

    for (int tile = blockIdx.x; tile < ntiles; tile += gridDim.x) {
        int mbase = tile * BM;

        // ---- A: load X rows (64 x 128), split to bf16 hi/lo ----
        {
            int row = mbase + ar;
#pragma unroll
            for (int k = ak0; k < ak0 + 32; k += 4) {
                float vv[4];
                if (row < n) {
                    if constexpr (sizeof(TIn) == 4) {
                        float4 v = *(const float4*)((const float*)X + (size_t)row * IN_DIM + k);
                        vv[0] = v.x; vv[1] = v.y; vv[2] = v.z; vv[3] = v.w;
                    } else {
                        uint2 u = *(const uint2*)((const __half*)X + (size_t)row * IN_DIM + k);
                        float2 f0 = __half22float2(*(__half2*)&u.x);
                        float2 f1 = __half22float2(*(__half2*)&u.y);
                        vv[0] = f0.x; vv[1] = f0.y; vv[2] = f1.x; vv[3] = f1.y;
                    }
                } else {
                    vv[0] = vv[1] = vv[2] = vv[3] = 0.0f;
                }
                __nv_bfloat16 h0 = __float2bfloat16_rn(vv[0]);
                __nv_bfloat16 h1 = __float2bfloat16_rn(vv[1]);
                __nv_bfloat16 h2 = __float2bfloat16_rn(vv[2]);
                __nv_bfloat16 h3 = __float2bfloat16_rn(vv[3]);
                __nv_bfloat16 l0 = __float2bfloat16_rn(vv[0] - __bfloat162float(h0));
                __nv_bfloat16 l1 = __float2bfloat16_rn(vv[1] - __bfloat162float(h1));
                __nv_bfloat16 l2 = __float2bfloat16_rn(vv[2] - __bfloat162float(h2));
                __nv_bfloat16 l3 = __float2bfloat16_rn(vv[3] - __bfloat162float(h3));
                uint2 hv; hv.x = pack2(h0, h1); hv.y = pack2(h2, h3);
                uint2 lv; lv.x = pack2(l0, l1); lv.y = pack2(l2, l3);
                *(uint2*)(ahp + k * 2) = hv;
                *(uint2*)(alp + k * 2) = lv;
            }
        }
        __syncthreads();

        float acc[2][NF][4];
#pragma unroll
        for (int mi = 0; mi < 2; mi++)
#pragma unroll
            for (int nf = 0; nf < NF; nf++)
#pragma unroll
                for (int q = 0; q < 4; q++) acc[mi][nf][q] = 0.0f;

        Frags<NC> f[2];
        load_frags<NC>(f[0], a_addr0, b_addr0, AL - AH, BL - BH, 0, PITCH);

#pragma unroll
        for (int ks = 0; ks < 8; ks++) {
            if (ks + 1 < 8)
                load_frags<NC>(f[(ks + 1) & 1], a_addr0, b_addr0, AL - AH, BL - BH, ks + 1, PITCH);
            Frags<NC>& c = f[ks & 1];
#pragma unroll
            for (int mi = 0; mi < 2; mi++)
#pragma unroll
                for (int nf = 0; nf < NF; nf++) {
                    mma_bf16(acc[mi][nf], c.ah[mi], c.bh[nf]);
                    mma_bf16(acc[mi][nf], c.ah[mi], c.bl[nf]);
                    mma_bf16(acc[mi][nf], c.al[mi], c.bh[nf]);
                }
        }

        // ---- epilogue: fp16 stores ----
#pragma unroll
        for (int mi = 0; mi < 2; mi++) {
            int r0 = mbase + m0 + mi * 16 + (lane >> 2);
#pragma unroll
            for (int nf = 0; nf < NF; nf++) {
                int col = n0 + nf * 8 + 2 * (lane & 3);
                if (r0 < n) {
                    __half2 v = __floats2half2_rn(acc[mi][nf][0], acc[mi][nf][1]);
                    *(__half2*)(G + (size_t)r0 * NC + col) = v;
                }
                if (r0 + 8 < n) {
                    __half2 v = __floats2half2_rn(acc[mi][nf][2], acc[mi][nf][3]);
                    *(__half2*)(G + (size_t)(r0 + 8) * NC + col) = v;
                }
            }
        }
        __syncthreads();   // all LDSM reads of A done before next tile overwrites
    }
}

// -------- aggregation: OUT[i] = act(dinv[i]*(sum_j dinv[j]*G[j] + dinv[i]*G[i]) + bias)
template <int NC, bool RELU, typename OutT>
__global__ __launch_bounds__(256) void k_agg(
    const __half* __restrict__ G, const float* __restrict__ bias,
    OutT* __restrict__ OUT, int n)
{
    constexpr int V = NC / 32;            // halfs per lane (4 or 2)
    constexpr int V2 = V / 2;             // half2 per lane (2 or 1)
    int gw = (blockIdx.x * blockDim.x + threadIdx.x) >> 5;
    int lane = threadIdx.x & 31;
    if (gw >= n) return;

    float di = g_dinv[gw];

    float acc[V];
    {
        const __half2* ps = (const __half2*)(G + (size_t)gw * NC + lane * V);
#pragma unroll
        for (int q = 0; q < V2; q++) {
            float2 fv = __half22float2(ps[q]);
            acc[2 * q] = di * fv.x;
            acc[2 * q + 1] = di * fv.y;
        }
    }

    int s = g_rptr[gw], e = g_rptr[gw + 1];
    for (int base = s; base < e; base += 32) {
        int idx = base + lane;
        int sj = 0;
        float dj = 0.0f;
        if (idx < e) {
            sj = g_csr[idx];
            dj = g_dinv[sj];
        }
        int m = e - base; if (m > 32) m = 32;
        int j = 0;
        for (; j + 4 <= m; j += 4) {
            int s0 = __shfl_sync(0xffffffffu, sj, j);
            int s1 = __shfl_sync(0xffffffffu, sj, j + 1);
            int s2 = __shfl_sync(0xffffffffu, sj, j + 2);
            int s3 = __shfl_sync(0xffffffffu, sj, j + 3);
            float d0 = __shfl_sync(0xffffffffu, dj, j);
            float d1 = __shfl_sync(0xffffffffu, dj, j + 1);
            float d2 = __shfl_sync(0xffffffffu, dj, j + 2);
            float d3 = __shfl_sync(0xffffffffu, dj, j + 3);
            const __half2* p0 = (const __half2*)(G + (size_t)s0 * NC + lane * V);
            const __half2* p1 = (const __half2*)(G + (size_t)s1 * NC + lane * V);
            const __half2* p2 = (const __half2*)(G + (size_t)s2 * NC + lane * V);
            const __half2* p3 = (const __half2*)(G + (size_t)s3 * NC + lane * V);
#pragma unroll
            for (int q = 0; q < V2; q++) {
                float2 a = __half22float2(p0[q]);
                float2 b = __half22float2(p1[q]);
                float2 c = __half22float2(p2[q]);
                float2 d = __half22float2(p3[q]);
                acc[2 * q]     += d0 * a.x + d1 * b.x + d2 * c.x + d3 * d.x;
                acc[2 * q + 1] += d0 * a.y + d1 * b.y + d2 * c.y + d3 * d.y;
            }
        }
        for (; j < m; j++) {
            int s0 = __shfl_sync(0xffffffffu, sj, j);
            float d0 = __shfl_sync(0xffffffffu, dj, j);
            const __half2* p = (const __half2*)(G + (size_t)s0 * NC + lane * V);
#pragma unroll
            for (int q = 0; q < V2; q++) {
                float2 a = __half22float2(p[q]);
                acc[2 * q]     += d0 * a.x;
                acc[2 * q + 1] += d0 * a.y;
            }
        }
    }

    float bv[V];
#pragma unroll
    for (int q = 0; q < V2; q++) {
        float2 b = *(const float2*)(bias + lane * V + 2 * q);
        bv[2 * q] = b.x; bv[2 * q + 1] = b.y;
    }
    float r[V];
#pragma unroll
    for (int v = 0; v < V; v++) {
        r[v] = acc[v] * di + bv[v];
        if (RELU) r[v] = fmaxf(r[v], 0.0f);
    }
    if constexpr (sizeof(OutT) == 2) {
        __half2* po = (__half2*)((__half*)OUT + (size_t)gw * NC + lane * V);
#pragma unroll
        for (int q = 0; q < V2; q++)
            po[q] = __floats2half2_rn(r[2 * q], r[2 * q + 1]);
    } else {
        float* po = (float*)OUT + (size_t)gw * NC + lane * V;
#pragma unroll
        for (int q = 0; q < V2; q++) {
            float2 o; o.x = r[2 * q]; o.y = r[2 * q + 1];
            *(float2*)(po + 2 * q) = o;
        }
    }
}

// ---------------- launch ----------------
extern "C" void kernel_launch(void* const* d_in, const int* in_sizes, int n_in,
                              void* d_out, int out_size)
{
    const float* x  = (const float*)d_in[0];
    const void*  ei = d_in[1];
    const float* W1 = (const float*)d_in[2];
    const float* b1 = (const float*)d_in[3];
    const float* W2 = (const float*)d_in[4];
    const float* b2 = (const float*)d_in[5];
    float* out = (float*)d_out;

    int n = in_sizes[0] / IN_DIM;
    int E = in_sizes[1] / 2;

    __half *g1p, *h1p, *g2p;
    cudaGetSymbolAddress((void**)&g1p, g_g1);
    cudaGetSymbolAddress((void**)&h1p, g_h1);
    cudaGetSymbolAddress((void**)&g2p, g_g2);
    __nv_bfloat16 *w1s, *w2s;
    cudaGetSymbolAddress((void**)&w1s, g_w1s);
    cudaGetSymbolAddress((void**)&w2s, g_w2s);

    const int smem1 = 2 * 64 * 272 + 2 * 128 * 272;   // 104448 -> 2 CTAs/SM
    const int smem2 = 2 * 64 * 272 + 2 * 64 * 272;    //  69632
    cudaFuncSetAttribute((const void*)k_gemm_mma<HID_DIM, float>,
                         cudaFuncAttributeMaxDynamicSharedMemorySize, smem1);
    cudaFuncSetAttribute((const void*)k_gemm_mma<OUT_DIM, __half>,
                         cudaFuncAttributeMaxDynamicSharedMemorySize, smem2);

    int nb1024 = (n + 1023) / 1024;
    int ntiles = (n + 63) / 64;
    const int PGRID = 296;                 // 2 CTAs x 148 SMs, persistent
    int pgrid = (ntiles < PGRID) ? ntiles : PGRID;
    int igrid = (n > HID_DIM * IN_DIM + OUT_DIM * HID_DIM ? n
                 : HID_DIM * IN_DIM + OUT_DIM * HID_DIM);

    k_detect<<<1, 1>>>(ei);                                            // 0
    k_init<<<(igrid + 255) / 256, 256>>>(W1, W2, n);                   // 1
    k_convcnt<<<(E + 255) / 256, 256>>>(ei, E);                        // 2
    k_gemm_mma<HID_DIM, float><<<pgrid, 256, smem1>>>(x, w1s, g1p, n, ntiles); // 3

    k_scanA<<<nb1024, 1024>>>(n);
    k_scanB<<<1, 128>>>(nb1024);
    k_scanC<<<(n + 255) / 256, 256>>>(n, E);
    k_scatter<<<(E + 255) / 256, 256>>>(E);

    k_agg<HID_DIM, true, __half><<<(n * 32 + 255) / 256, 256>>>(g1p, b1, h1p, n);
    k_gemm_mma<OUT_DIM, __half><<<pgrid, 256, smem2>>>(h1p, w2s, g2p, n, ntiles);
    k_agg<OUT_DIM, false, float><<<(n * 32 + 255) / 256, 256>>>(g2p, b2, out, n);
}

// round 11
// speedup vs baseline: 1.7082x; 1.0532x over previous
#include <cuda_runtime.h>
#include <cuda_bf16.h>
#include <cuda_fp16.h>
#include <cstdint>

// ---------------- problem constants ----------------
#define N_MAX 100000
#define E_MAX 1600000
#define IN_DIM 128
#define HID_DIM 128
#define OUT_DIM 64

typedef unsigned long long u64;

// ---------------- device scratch ----------------
__device__ int   g_cnt[N_MAX];
__device__ int   g_rptr[N_MAX + 1];
__device__ int   g_cursor[N_MAX];
__device__ int   g_part[256];
__device__ float g_dinv[N_MAX];
__device__ int   g_csr[E_MAX];
// fp16 message/feature buffers (halved gather traffic)
__device__ __align__(16) __half g_g1[(size_t)N_MAX * HID_DIM];
__device__ __align__(16) __half g_h1[(size_t)N_MAX * HID_DIM];
__device__ __align__(16) __half g_g2[(size_t)N_MAX * OUT_DIM];
// W1 pre-split bf16 hi/lo, layout Wt[c][k]; W2 pre-split fp16 hi/lo
__device__ __align__(16) __nv_bfloat16 g_w1s[2 * HID_DIM * IN_DIM];
__device__ __align__(16) __half        g_w2s[2 * OUT_DIM * HID_DIM];

// ---------------- PTX helpers (baseline ISA: ldmatrix + mma.sync) ----------
__device__ __forceinline__ uint32_t smem_u32(const void* p) {
    uint32_t a;
    asm("{ .reg .u64 t; cvta.to.shared.u64 t, %1; cvt.u32.u64 %0, t; }" : "=r"(a) : "l"(p));
    return a;
}
__device__ __forceinline__ void ldsm4(uint32_t* r, uint32_t addr) {
    asm volatile("ldmatrix.sync.aligned.m8n8.x4.shared.b16 {%0,%1,%2,%3}, [%4];"
                 : "=r"(r[0]), "=r"(r[1]), "=r"(r[2]), "=r"(r[3]) : "r"(addr));
}
__device__ __forceinline__ void mma_bf16(float* c, const uint32_t* a, const uint32_t* b) {
    asm volatile(
        "mma.sync.aligned.m16n8k16.row.col.f32.bf16.bf16.f32 "
        "{%0,%1,%2,%3}, {%4,%5,%6,%7}, {%8,%9}, {%0,%1,%2,%3};"
        : "+f"(c[0]), "+f"(c[1]), "+f"(c[2]), "+f"(c[3])
        : "r"(a[0]), "r"(a[1]), "r"(a[2]), "r"(a[3]), "r"(b[0]), "r"(b[1]));
}
__device__ __forceinline__ void mma_f16(float* c, const uint32_t* a, const uint32_t* b) {
    asm volatile(
        "mma.sync.aligned.m16n8k16.row.col.f32.f16.f16.f32 "
        "{%0,%1,%2,%3}, {%4,%5,%6,%7}, {%8,%9}, {%0,%1,%2,%3};"
        : "+f"(c[0]), "+f"(c[1]), "+f"(c[2]), "+f"(c[3])
        : "r"(a[0]), "r"(a[1]), "r"(a[2]), "r"(a[3]), "r"(b[0]), "r"(b[1]));
}
__device__ __forceinline__ uint32_t pack2(__nv_bfloat16 a, __nv_bfloat16 b) {
    return (uint32_t)__bfloat16_as_ushort(a) | ((uint32_t)__bfloat16_as_ushort(b) << 16);
}

// per-warp int64-vs-int32 edge dtype detection (lane 0 reads 8 words, shfl)
__device__ __forceinline__ int detect_is64(const void* p) {
    int ok = 1;
    if ((threadIdx.x & 31) == 0) {
        const long long* q = (const long long*)p;
#pragma unroll
        for (int i = 0; i < 8; i++) {
            long long v = q[i];
            if (v < 0 || v >= (long long)N_MAX * 4) ok = 0;
        }
    }
    return __shfl_sync(0xffffffffu, ok, 0);
}

// ---------------- fused init: zero counters + pre-split both weights -------
__global__ void k_init(const float* __restrict__ W1, const float* __restrict__ W2, int n) {
    int i = blockIdx.x * blockDim.x + threadIdx.x;
    if (i < n) g_cnt[i] = 0;
    if (i < HID_DIM * IN_DIM) {
        int c = i >> 7, k = i & 127;
        float w = W1[(size_t)k * HID_DIM + c];
        __nv_bfloat16 h = __float2bfloat16_rn(w);
        __nv_bfloat16 l = __float2bfloat16_rn(w - __bfloat162float(h));
        g_w1s[c * IN_DIM + k] = h;
        g_w1s[HID_DIM * IN_DIM + c * IN_DIM + k] = l;
    } else if (i < HID_DIM * IN_DIM + OUT_DIM * HID_DIM) {
        int j = i - HID_DIM * IN_DIM;
        int c = j >> 7, k = j & 127;
        float w = W2[(size_t)k * OUT_DIM + c];
        __half h = __float2half_rn(w);
        __half l = __float2half_rn(w - __half2float(h));
        g_w2s[c * HID_DIM + k] = h;
        g_w2s[OUT_DIM * HID_DIM + c * HID_DIM + k] = l;
    }
}

// ---------------- count (reads dst half of original edge buffer) -----------
__global__ void k_convcnt(const void* p, int E) {
    int is64 = detect_is64(p);
    int e = blockIdx.x * blockDim.x + threadIdx.x;
    if (e >= E) return;
    int d;
    if (is64) d = (int)((const long long*)p)[(size_t)E + e];
    else      d = ((const int*)p)[(size_t)E + e];
    atomicAdd(&g_cnt[d], 1);
}

// ---------------- scan / scatter ----------------
__global__ void k_scanA(int n) {
    __shared__ int sh[1024];
    int t = threadIdx.x;
    int idx = blockIdx.x * 1024 + t;
    int v = (idx < n) ? g_cnt[idx] : 0;
    sh[t] = v;
    __syncthreads();
#pragma unroll
    for (int off = 1; off < 1024; off <<= 1) {
        int add = (t >= off) ? sh[t - off] : 0;
        __syncthreads();
        sh[t] += add;
        __syncthreads();
    }
    int incl = sh[t];
    if (idx < n) g_rptr[idx] = incl - v;
    if (t == 1023) g_part[blockIdx.x] = incl;   // inclusive block total
}

// scanC: adds block-prefix (computed inline from g_part totals) + dinv + cursor
__global__ void k_scanC(int n, int E) {
    __shared__ int bsum;
    int b = blockIdx.x;                 // 256-thread blocks
    int npart = b >> 2;                 // # of 1024-blocks strictly before this chunk
    if (threadIdx.x < 32) {
        int acc = 0;
        for (int i = threadIdx.x; i < npart; i += 32) acc += g_part[i];
#pragma unroll
        for (int o = 16; o; o >>= 1) acc += __shfl_down_sync(0xffffffffu, acc, o);
        if (threadIdx.x == 0) bsum = acc;
    }
    __syncthreads();
    int idx = b * 256 + threadIdx.x;
    if (idx < n) {
        int r = g_rptr[idx] + bsum;
        g_rptr[idx] = r;
        g_cursor[idx] = r;
        g_dinv[idx] = rsqrtf((float)g_cnt[idx] + 1.0f);
    }
    if (idx == 0) g_rptr[n] = E;
}

__global__ void k_scatter(const void* p, int E) {
    int is64 = detect_is64(p);
    int e = blockIdx.x * blockDim.x + threadIdx.x;
    if (e >= E) return;
    int s, d;
    if (is64) {
        const long long* q = (const long long*)p;
        s = (int)q[e];
        d = (int)q[(size_t)E + e];
    } else {
        const int* q = (const int*)p;
        s = q[e];
        d = q[(size_t)E + e];
    }
    int pos = atomicAdd(&g_cursor[d], 1);
    g_csr[pos] = s;
}

// ---------------- GEMM1: G(fp16) = X(fp32) @ W1, split-bf16 3-product ------
struct Frags128 {
    uint32_t ah[2][4], al[2][4];
    uint32_t bh[4][2], bl[4][2];
};

__device__ __forceinline__ void load_frags128(
    Frags128& f, uint32_t a_addr0, uint32_t b_addr0,
    uint32_t a_lo_off, uint32_t b_lo_off, int ks, int PITCH)
{
    uint32_t koff = ks * 32;
#pragma unroll
    for (int mi = 0; mi < 2; mi++) {
        ldsm4(f.ah[mi], a_addr0 + mi * 16 * PITCH + koff);
        ldsm4(f.al[mi], a_addr0 + a_lo_off + mi * 16 * PITCH + koff);
    }
#pragma unroll
    for (int pr = 0; pr < 2; pr++) {
        uint32_t r[4];
        ldsm4(r, b_addr0 + pr * 16 * PITCH + koff);
        f.bh[2 * pr][0] = r[0]; f.bh[2 * pr][1] = r[1];
        f.bh[2 * pr + 1][0] = r[2]; f.bh[2 * pr + 1][1] = r[3];
        ldsm4(r, b_addr0 + b_lo_off + pr * 16 * PITCH + koff);
        f.bl[2 * pr][0] = r[0]; f.bl[2 * pr][1] = r[1];
        f.bl[2 * pr + 1][0] = r[2]; f.bl[2 * pr + 1][1] = r[3];
    }
}

__global__ __launch_bounds__(256, 2) void k_gemm1(
    const float* __restrict__ X, const __nv_bfloat16* __restrict__ Ws,
    __half* __restrict__ G, int n, int ntiles)
{
    extern __shared__ char smem[];
    constexpr int NC = HID_DIM;
    constexpr int PITCH = 272;
    constexpr int BM = 64;
    constexpr int AH = 0;
    constexpr int AL = AH + BM * PITCH;
    constexpr int BH = AL + BM * PITCH;
    constexpr int BL = BH + NC * PITCH;

    uint32_t sb = smem_u32(smem);
    int tid = threadIdx.x;

    // B once per CTA
    {
        constexpr int BU4 = NC * 128 * 2 / 16;
        const uint4* ws4 = (const uint4*)Ws;
#pragma unroll
        for (int r = 0; r < BU4 / 256; r++) {
            int li = tid + r * 256;
            int c = li >> 4;
            int ch = li & 15;
            *(uint4*)(smem + BH + c * PITCH + ch * 16) = ws4[li];
            *(uint4*)(smem + BL + c * PITCH + ch * 16) = ws4[BU4 + li];
        }
    }

    int wid = tid >> 5;
    int lane = tid & 31;
    int wm = wid & 1;
    int wn = wid >> 1;
    int m0 = wm * 32;
    int n0 = wn * (NC / 4);

    uint32_t a_addr0 = sb + AH + (uint32_t)(m0 + (lane & 15)) * PITCH + ((lane >> 4) * 16);
    uint32_t b_row   = (uint32_t)(n0 + (lane & 7) + ((lane >> 4) & 1) * 8);
    uint32_t b_addr0 = sb + BH + b_row * PITCH + (((lane >> 3) & 1) * 16);

    int ar = tid >> 2;
    int ak0 = (tid & 3) * 32;
    char* ahp = smem + AH + ar * PITCH;
    char* alp = smem + AL + ar * PITCH;

    for (int tile = blockIdx.x; tile < ntiles; tile += gridDim.x) {
        int mbase = tile * BM;
        {
            int row = mbase + ar;
#pragma unroll
            for (int k = ak0; k < ak0 + 32; k += 4) {
                float4 v = make_float4(0.f, 0.f, 0.f, 0.f);
                if (row < n) v = *(const float4*)(X + (size_t)row * IN_DIM + k);
                __nv_bfloat16 h0 = __float2bfloat16_rn(v.x);
                __nv_bfloat16 h1 = __float2bfloat16_rn(v.y);
                __nv_bfloat16 h2 = __float2bfloat16_rn(v.z);
                __nv_bfloat16 h3 = __float2bfloat16_rn(v.w);
                __nv_bfloat16 l0 = __float2bfloat16_rn(v.x - __bfloat162float(h0));
                __nv_bfloat16 l1 = __float2bfloat16_rn(v.y - __bfloat162float(h1));
                __nv_bfloat16 l2 = __float2bfloat16_rn(v.z - __bfloat162float(h2));
                __nv_bfloat16 l3 = __float2bfloat16_rn(v.w - __bfloat162float(h3));
                uint2 hv; hv.x = pack2(h0, h1); hv.y = pack2(h2, h3);
                uint2 lv; lv.x = pack2(l0, l1); lv.y = pack2(l2, l3);
                *(uint2*)(ahp + k * 2) = hv;
                *(uint2*)(alp + k * 2) = lv;
            }
        }
        __syncthreads();

        float acc[2][4][4];
#pragma unroll
        for (int mi = 0; mi < 2; mi++)
#pragma unroll
            for (int nf = 0; nf < 4; nf++)
#pragma unroll
                for (int q = 0; q < 4; q++) acc[mi][nf][q] = 0.0f;

        Frags128 f[2];
        load_frags128(f[0], a_addr0, b_addr0, AL - AH, BL - BH, 0, PITCH);
#pragma unroll
        for (int ks = 0; ks < 8; ks++) {
            if (ks + 1 < 8)
                load_frags128(f[(ks + 1) & 1], a_addr0, b_addr0, AL - AH, BL - BH, ks + 1, PITCH);
            Frags128& c = f[ks & 1];
#pragma unroll
            for (int mi = 0; mi < 2; mi++)
#pragma unroll
                for (int nf = 0; nf < 4; nf++) {
                    mma_bf16(acc[mi][nf], c.ah[mi], c.bh[nf]);
                    mma_bf16(acc[mi][nf], c.ah[mi], c.bl[nf]);
                    mma_bf16(acc[mi][nf], c.al[mi], c.bh[nf]);
                }
        }

#pragma unroll
        for (int mi = 0; mi < 2; mi++) {
            int r0 = mbase + m0 + mi * 16 + (lane >> 2);
#pragma unroll
            for (int nf = 0; nf < 4; nf++) {
                int col = n0 + nf * 8 + 2 * (lane & 3);
                if (r0 < n) {
                    __half2 v = __floats2half2_rn(acc[mi][nf][0], acc[mi][nf][1]);
                    *(__half2*)(G + (size_t)r0 * NC + col) = v;
                }
                if (r0 + 8 < n) {
                    __half2 v = __floats2half2_rn(acc[mi][nf][2], acc[mi][nf][3]);
                    *(__half2*)(G + (size_t)(r0 + 8) * NC + col) = v;
                }
            }
        }
        __syncthreads();
    }
}

// ---------------- GEMM2: G2(fp16) = h1(fp16, exact A) @ W2, fp16 2-product -
__global__ __launch_bounds__(256, 4) void k_gemm2(
    const __half* __restrict__ X, const __half* __restrict__ Ws,
    __half* __restrict__ G, int n, int ntiles)
{
    extern __shared__ char smem[];
    constexpr int NC = OUT_DIM;
    constexpr int PITCH = 272;
    constexpr int BM = 64;
    constexpr int AH = 0;
    constexpr int BH = AH + BM * PITCH;        // A fp16, single
    constexpr int BL = BH + NC * PITCH;

    uint32_t sb = smem_u32(smem);
    int tid = threadIdx.x;

    // B once per CTA: W2 hi/lo fp16 (NC x 128 each)
    {
        constexpr int BU4 = NC * 128 * 2 / 16;  // 1024
        const uint4* ws4 = (const uint4*)Ws;
#pragma unroll
        for (int r = 0; r < BU4 / 256; r++) {
            int li = tid + r * 256;
            int c = li >> 4;
            int ch = li & 15;
            *(uint4*)(smem + BH + c * PITCH + ch * 16) = ws4[li];
            *(uint4*)(smem + BL + c * PITCH + ch * 16) = ws4[BU4 + li];
        }
    }

    int wid = tid >> 5;
    int lane = tid & 31;
    int wm = wid & 1;
    int wn = wid >> 1;
    int m0 = wm * 32;
    int n0 = wn * (NC / 4);                     // 16 cols per warp

    uint32_t a_addr0 = sb + AH + (uint32_t)(m0 + (lane & 15)) * PITCH + ((lane >> 4) * 16);
    uint32_t b_row   = (uint32_t)(n0 + (lane & 7) + ((lane >> 4) & 1) * 8);
    uint32_t b_addr0 = sb + BH + b_row * PITCH + (((lane >> 3) & 1) * 16);

    for (int tile = blockIdx.x; tile < ntiles; tile += gridDim.x) {
        int mbase = tile * BM;
        // A: raw fp16 copy, 64 rows x 256B = 1024 uint4
        {
#pragma unroll
            for (int r = 0; r < 4; r++) {
                int li = tid + r * 256;
                int row = li >> 4;
                int ch = li & 15;
                uint4 v = make_uint4(0, 0, 0, 0);
                if (mbase + row < n)
                    v = *(const uint4*)((const char*)(X + (size_t)(mbase + row) * HID_DIM) + ch * 16);
                *(uint4*)(smem + AH + row * PITCH + ch * 16) = v;
            }
        }
        __syncthreads();

        float acc[2][2][4];
#pragma unroll
        for (int mi = 0; mi < 2; mi++)
#pragma unroll
            for (int nf = 0; nf < 2; nf++)
#pragma unroll
                for (int q = 0; q < 4; q++) acc[mi][nf][q] = 0.0f;

#pragma unroll
        for (int ks = 0; ks < 8; ks++) {
            uint32_t koff = ks * 32;
            uint32_t a[2][4];
            ldsm4(a[0], a_addr0 + koff);
            ldsm4(a[1], a_addr0 + 16 * PITCH + koff);
            uint32_t bh[2][2], bl[2][2];
            {
                uint32_t r[4];
                ldsm4(r, b_addr0 + koff);
                bh[0][0] = r[0]; bh[0][1] = r[1];
                bh[1][0] = r[2]; bh[1][1] = r[3];
                ldsm4(r, b_addr0 + (BL - BH) + koff);
                bl[0][0] = r[0]; bl[0][1] = r[1];
                bl[1][0] = r[2]; bl[1][1] = r[3];
            }
#pragma unroll
            for (int mi = 0; mi < 2; mi++)
#pragma unroll
                for (int nf = 0; nf < 2; nf++) {
                    mma_f16(acc[mi][nf], a[mi], bh[nf]);
                    mma_f16(acc[mi][nf], a[mi], bl[nf]);
                }
        }

#pragma unroll
        for (int mi = 0; mi < 2; mi++) {
            int r0 = mbase + m0 + mi * 16 + (lane >> 2);
#pragma unroll
            for (int nf = 0; nf < 2; nf++) {
                int col = n0 + nf * 8 + 2 * (lane & 3);
                if (r0 < n) {
                    __half2 v = __floats2half2_rn(acc[mi][nf][0], acc[mi][nf][1]);
                    *(__half2*)(G + (size_t)r0 * NC + col) = v;
                }
                if (r0 + 8 < n) {
                    __half2 v = __floats2half2_rn(acc[mi][nf][2], acc[mi][nf][3]);
                    *(__half2*)(G + (size_t)(r0 + 8) * NC + col) = v;
                }
            }
        }
        __syncthreads();
    }
}

// -------- aggregation: OUT[i] = act(dinv[i]*(sum_j dinv[j]*G[j] + dinv[i]*G[i]) + bias)
template <int NC, bool RELU, typename OutT>
__global__ __launch_bounds__(256) void k_agg(
    const __half* __restrict__ G, const float* __restrict__ bias,
    OutT* __restrict__ OUT, int n)
{
    constexpr int V = NC / 32;
    constexpr int V2 = V / 2;
    int gw = (blockIdx.x * blockDim.x + threadIdx.x) >> 5;
    int lane = threadIdx.x & 31;
    if (gw >= n) return;

    float di = g_dinv[gw];

    float acc[V];
    {
        const __half2* ps = (const __half2*)(G + (size_t)gw * NC + lane * V);
#pragma unroll
        for (int q = 0; q < V2; q++) {
            float2 fv = __half22float2(ps[q]);
            acc[2 * q] = di * fv.x;
            acc[2 * q + 1] = di * fv.y;
        }
    }

    int s = g_rptr[gw], e = g_rptr[gw + 1];
    for (int base = s; base < e; base += 32) {
        int idx = base + lane;
        int sj = 0;
        float dj = 0.0f;
        if (idx < e) {
            sj = g_csr[idx];
            dj = g_dinv[sj];
        }
        int m = e - base; if (m > 32) m = 32;
        int j = 0;
        for (; j + 4 <= m; j += 4) {
            int s0 = __shfl_sync(0xffffffffu, sj, j);
            int s1 = __shfl_sync(0xffffffffu, sj, j + 1);
            int s2 = __shfl_sync(0xffffffffu, sj, j + 2);
            int s3 = __shfl_sync(0xffffffffu, sj, j + 3);
            float d0 = __shfl_sync(0xffffffffu, dj, j);
            float d1 = __shfl_sync(0xffffffffu, dj, j + 1);
            float d2 = __shfl_sync(0xffffffffu, dj, j + 2);
            float d3 = __shfl_sync(0xffffffffu, dj, j + 3);
            const __half2* p0 = (const __half2*)(G + (size_t)s0 * NC + lane * V);
            const __half2* p1 = (const __half2*)(G + (size_t)s1 * NC + lane * V);
            const __half2* p2 = (const __half2*)(G + (size_t)s2 * NC + lane * V);
            const __half2* p3 = (const __half2*)(G + (size_t)s3 * NC + lane * V);
#pragma unroll
            for (int q = 0; q < V2; q++) {
                float2 a = __half22float2(p0[q]);
                float2 b = __half22float2(p1[q]);
                float2 c = __half22float2(p2[q]);
                float2 d = __half22float2(p3[q]);
                acc[2 * q]     += d0 * a.x + d1 * b.x + d2 * c.x + d3 * d.x;
                acc[2 * q + 1] += d0 * a.y + d1 * b.y + d2 * c.y + d3 * d.y;
            }
        }
        for (; j < m; j++) {
            int s0 = __shfl_sync(0xffffffffu, sj, j);
            float d0 = __shfl_sync(0xffffffffu, dj, j);
            const __half2* p = (const __half2*)(G + (size_t)s0 * NC + lane * V);
#pragma unroll
            for (int q = 0; q < V2; q++) {
                float2 a = __half22float2(p[q]);
                acc[2 * q]     += d0 * a.x;
                acc[2 * q + 1] += d0 * a.y;
            }
        }
    }

    float bv[V];
#pragma unroll
    for (int q = 0; q < V2; q++) {
        float2 b = *(const float2*)(bias + lane * V + 2 * q);
        bv[2 * q] = b.x; bv[2 * q + 1] = b.y;
    }
    float r[V];
#pragma unroll
    for (int v = 0; v < V; v++) {
        r[v] = acc[v] * di + bv[v];
        if (RELU) r[v] = fmaxf(r[v], 0.0f);
    }
    if constexpr (sizeof(OutT) == 2) {
        __half2* po = (__half2*)((__half*)OUT + (size_t)gw * NC + lane * V);
#pragma unroll
        for (int q = 0; q < V2; q++)
            po[q] = __floats2half2_rn(r[2 * q], r[2 * q + 1]);
    } else {
        float* po = (float*)OUT + (size_t)gw * NC + lane * V;
#pragma unroll
        for (int q = 0; q < V2; q++) {
            float2 o; o.x = r[2 * q]; o.y = r[2 * q + 1];
            *(float2*)(po + 2 * q) = o;
        }
    }
}

// ---------------- launch ----------------
extern "C" void kernel_launch(void* const* d_in, const int* in_sizes, int n_in,
                              void* d_out, int out_size)
{
    const float* x  = (const float*)d_in[0];
    const void*  ei = d_in[1];
    const float* W1 = (const float*)d_in[2];
    const float* b1 = (const float*)d_in[3];
    const float* W2 = (const float*)d_in[4];
    const float* b2 = (const float*)d_in[5];
    float* out = (float*)d_out;

    int n = in_sizes[0] / IN_DIM;
    int E = in_sizes[1] / 2;

    __half *g1p, *h1p, *g2p;
    cudaGetSymbolAddress((void**)&g1p, g_g1);
    cudaGetSymbolAddress((void**)&h1p, g_h1);
    cudaGetSymbolAddress((void**)&g2p, g_g2);
    __nv_bfloat16* w1s;
    __half* w2s;
    cudaGetSymbolAddress((void**)&w1s, g_w1s);
    cudaGetSymbolAddress((void**)&w2s, g_w2s);

    const int smem1 = 2 * 64 * 272 + 2 * 128 * 272;   // 104448 -> 2 CTAs/SM
    const int smem2 = 64 * 272 + 2 * 64 * 272;        //  52224 -> 4 CTAs/SM
    cudaFuncSetAttribute((const void*)k_gemm1, cudaFuncAttributeMaxDynamicSharedMemorySize, smem1);
    cudaFuncSetAttribute((const void*)k_gemm2, cudaFuncAttributeMaxDynamicSharedMemorySize, smem2);

    int nb1024 = (n + 1023) / 1024;
    int ntiles = (n + 63) / 64;
    int pg1 = (ntiles < 296) ? ntiles : 296;
    int pg2 = (ntiles < 592) ? ntiles : 592;
    int igrid = (n > HID_DIM * IN_DIM + OUT_DIM * HID_DIM ? n
                 : HID_DIM * IN_DIM + OUT_DIM * HID_DIM);

    k_init<<<(igrid + 255) / 256, 256>>>(W1, W2, n);          // 0
    k_convcnt<<<(E + 255) / 256, 256>>>(ei, E);               // 1
    k_scanA<<<nb1024, 1024>>>(n);                             // 2
    k_gemm1<<<pg1, 256, smem1>>>(x, w1s, g1p, n, ntiles);     // 3 (ncu slot)
    k_scanC<<<(n + 255) / 256, 256>>>(n, E);                  // 4
    k_scatter<<<(E + 255) / 256, 256>>>(ei, E);               // 5
    k_agg<HID_DIM, true, __half><<<(n * 32 + 255) / 256, 256>>>(g1p, b1, h1p, n);  // 6
    k_gemm2<<<pg2, 256, smem2>>>(h1p, w2s, g2p, n, ntiles);   // 7
    k_agg<OUT_DIM, false, float><<<(n * 32 + 255) / 256, 256>>>(g2p, b2, out, n);  // 8
}

// round 12
// speedup vs baseline: 1.8262x; 1.0691x over previous
#include <cuda_runtime.h>
#include <cuda_bf16.h>
#include <cuda_fp16.h>
#include <cstdint>

// ---------------- problem constants ----------------
#define N_MAX 100000
#define E_MAX 1600000
#define IN_DIM 128
#define HID_DIM 128
#define OUT_DIM 64

typedef unsigned long long u64;

// ---------------- device scratch ----------------
__device__ int   g_cnt[N_MAX];
__device__ int   g_rptr[N_MAX + 1];
__device__ int   g_cursor[N_MAX];
__device__ int   g_part[256];
__device__ float g_dinv[N_MAX];
__device__ int   g_csr[E_MAX];
// fp16 message/feature buffers
__device__ __align__(16) __half g_g1[(size_t)N_MAX * HID_DIM];
__device__ __align__(16) __half g_h1[(size_t)N_MAX * HID_DIM];
__device__ __align__(16) __half g_g2[(size_t)N_MAX * OUT_DIM];
// W1 and W2 pre-split fp16 hi/lo, layout Wt[c][k] (k contiguous), hi block then lo
__device__ __align__(16) __half g_w1s[2 * HID_DIM * IN_DIM];
__device__ __align__(16) __half g_w2s[2 * OUT_DIM * HID_DIM];

// ---------------- PTX helpers (baseline ISA: ldmatrix + mma.sync) ----------
__device__ __forceinline__ uint32_t smem_u32(const void* p) {
    uint32_t a;
    asm("{ .reg .u64 t; cvta.to.shared.u64 t, %1; cvt.u32.u64 %0, t; }" : "=r"(a) : "l"(p));
    return a;
}
__device__ __forceinline__ void ldsm4(uint32_t* r, uint32_t addr) {
    asm volatile("ldmatrix.sync.aligned.m8n8.x4.shared.b16 {%0,%1,%2,%3}, [%4];"
                 : "=r"(r[0]), "=r"(r[1]), "=r"(r[2]), "=r"(r[3]) : "r"(addr));
}
__device__ __forceinline__ void mma_f16(float* c, const uint32_t* a, const uint32_t* b) {
    asm volatile(
        "mma.sync.aligned.m16n8k16.row.col.f32.f16.f16.f32 "
        "{%0,%1,%2,%3}, {%4,%5,%6,%7}, {%8,%9}, {%0,%1,%2,%3};"
        : "+f"(c[0]), "+f"(c[1]), "+f"(c[2]), "+f"(c[3])
        : "r"(a[0]), "r"(a[1]), "r"(a[2]), "r"(a[3]), "r"(b[0]), "r"(b[1]));
}

// per-warp int64-vs-int32 edge dtype detection
__device__ __forceinline__ int detect_is64(const void* p) {
    int ok = 1;
    if ((threadIdx.x & 31) == 0) {
        const long long* q = (const long long*)p;
#pragma unroll
        for (int i = 0; i < 8; i++) {
            long long v = q[i];
            if (v < 0 || v >= (long long)N_MAX * 4) ok = 0;
        }
    }
    return __shfl_sync(0xffffffffu, ok, 0);
}

// ---------------- fused init: zero counters + pre-split both weights -------
__global__ void k_init(const float* __restrict__ W1, const float* __restrict__ W2, int n) {
    int i = blockIdx.x * blockDim.x + threadIdx.x;
    if (i < n) g_cnt[i] = 0;
    if (i < HID_DIM * IN_DIM) {
        int c = i >> 7, k = i & 127;
        float w = W1[(size_t)k * HID_DIM + c];
        __half h = __float2half_rn(w);
        __half l = __float2half_rn(w - __half2float(h));
        g_w1s[c * IN_DIM + k] = h;
        g_w1s[HID_DIM * IN_DIM + c * IN_DIM + k] = l;
    } else if (i < HID_DIM * IN_DIM + OUT_DIM * HID_DIM) {
        int j = i - HID_DIM * IN_DIM;
        int c = j >> 7, k = j & 127;
        float w = W2[(size_t)k * OUT_DIM + c];
        __half h = __float2half_rn(w);
        __half l = __float2half_rn(w - __half2float(h));
        g_w2s[c * HID_DIM + k] = h;
        g_w2s[OUT_DIM * HID_DIM + c * HID_DIM + k] = l;
    }
}

// ---------------- count (reads dst half of original edge buffer) -----------
__global__ void k_convcnt(const void* p, int E) {
    int is64 = detect_is64(p);
    int e = blockIdx.x * blockDim.x + threadIdx.x;
    if (e >= E) return;
    int d;
    if (is64) d = (int)((const long long*)p)[(size_t)E + e];
    else      d = ((const int*)p)[(size_t)E + e];
    atomicAdd(&g_cnt[d], 1);
}

// ---------------- scan / scatter ----------------
__global__ void k_scanA(int n) {
    __shared__ int sh[1024];
    int t = threadIdx.x;
    int idx = blockIdx.x * 1024 + t;
    int v = (idx < n) ? g_cnt[idx] : 0;
    sh[t] = v;
    __syncthreads();
#pragma unroll
    for (int off = 1; off < 1024; off <<= 1) {
        int add = (t >= off) ? sh[t - off] : 0;
        __syncthreads();
        sh[t] += add;
        __syncthreads();
    }
    int incl = sh[t];
    if (idx < n) g_rptr[idx] = incl - v;
    if (t == 1023) g_part[blockIdx.x] = incl;
}

__global__ void k_scanC(int n, int E) {
    __shared__ int bsum;
    int b = blockIdx.x;
    int npart = b >> 2;
    if (threadIdx.x < 32) {
        int acc = 0;
        for (int i = threadIdx.x; i < npart; i += 32) acc += g_part[i];
#pragma unroll
        for (int o = 16; o; o >>= 1) acc += __shfl_down_sync(0xffffffffu, acc, o);
        if (threadIdx.x == 0) bsum = acc;
    }
    __syncthreads();
    int idx = b * 256 + threadIdx.x;
    if (idx < n) {
        int r = g_rptr[idx] + bsum;
        g_rptr[idx] = r;
        g_cursor[idx] = r;
        g_dinv[idx] = rsqrtf((float)g_cnt[idx] + 1.0f);
    }
    if (idx == 0) g_rptr[n] = E;
}

__global__ void k_scatter(const void* p, int E) {
    int is64 = detect_is64(p);
    int e = blockIdx.x * blockDim.x + threadIdx.x;
    if (e >= E) return;
    int s, d;
    if (is64) {
        const long long* q = (const long long*)p;
        s = (int)q[e];
        d = (int)q[(size_t)E + e];
    } else {
        const int* q = (const int*)p;
        s = q[e];
        d = q[(size_t)E + e];
    }
    int pos = atomicAdd(&g_cursor[d], 1);
    g_csr[pos] = s;
}

// ---------------- GEMM: G(fp16) = A @ W, fp16 A (exact/quantized), W hi/lo -
// Persistent CTAs. A single fp16 buffer in smem; W hi+lo 2-product fp16 MMA.
// TIn = float (layer 1: quantize X->fp16 in prologue) or __half (layer 2: copy).
template <int NC, typename TIn>
__global__ __launch_bounds__(256, 2) void k_gemm(
    const TIn* __restrict__ X, const __half* __restrict__ Ws,
    __half* __restrict__ G, int n, int ntiles)
{
    extern __shared__ char smem[];
    constexpr int PITCH = 272;
    constexpr int BM = 64;
    constexpr int AH = 0;
    constexpr int BH = AH + BM * PITCH;
    constexpr int BL = BH + NC * PITCH;
    constexpr int NF = NC / 32;             // 4 (NC=128) or 2 (NC=64)

    uint32_t sb = smem_u32(smem);
    int tid = threadIdx.x;

    // ---- B once per CTA: W hi/lo fp16 (NC x 128 each) ----
    {
        constexpr int BU4 = NC * 128 * 2 / 16;
        const uint4* ws4 = (const uint4*)Ws;
#pragma unroll
        for (int r = 0; r < BU4 / 256; r++) {
            int li = tid + r * 256;
            int c = li >> 4;
            int ch = li & 15;
            *(uint4*)(smem + BH + c * PITCH + ch * 16) = ws4[li];
            *(uint4*)(smem + BL + c * PITCH + ch * 16) = ws4[BU4 + li];
        }
    }

    int wid = tid >> 5;
    int lane = tid & 31;
    int wm = wid & 1;
    int wn = wid >> 1;
    int m0 = wm * 32;
    int n0 = wn * (NC / 4);

    uint32_t a_addr0 = sb + AH + (uint32_t)(m0 + (lane & 15)) * PITCH + ((lane >> 4) * 16);
    uint32_t b_row   = (uint32_t)(n0 + (lane & 7) + ((lane >> 4) & 1) * 8);
    uint32_t b_addr0 = sb + BH + b_row * PITCH + (((lane >> 3) & 1) * 16);

    for (int tile = blockIdx.x; tile < ntiles; tile += gridDim.x) {
        int mbase = tile * BM;

        // ---- A prologue ----
        if constexpr (sizeof(TIn) == 4) {
            // fp32 -> fp16 quantize: thread handles row=tid>>2, 32 k values
            int ar = tid >> 2;
            int ak0 = (tid & 3) * 32;
            int row = mbase + ar;
            char* ap = smem + AH + ar * PITCH;
#pragma unroll
            for (int k = ak0; k < ak0 + 32; k += 4) {
                float4 v = make_float4(0.f, 0.f, 0.f, 0.f);
                if (row < n) v = *(const float4*)((const float*)X + (size_t)row * IN_DIM + k);
                __half2 p0 = __floats2half2_rn(v.x, v.y);
                __half2 p1 = __floats2half2_rn(v.z, v.w);
                uint2 u; u.x = *(uint32_t*)&p0; u.y = *(uint32_t*)&p1;
                *(uint2*)(ap + k * 2) = u;
            }
        } else {
            // raw fp16 copy: 64 rows x 256B = 1024 uint4
#pragma unroll
            for (int r = 0; r < 4; r++) {
                int li = tid + r * 256;
                int row = li >> 4;
                int ch = li & 15;
                uint4 v = make_uint4(0, 0, 0, 0);
                if (mbase + row < n)
                    v = *(const uint4*)((const char*)((const __half*)X + (size_t)(mbase + row) * IN_DIM) + ch * 16);
                *(uint4*)(smem + AH + row * PITCH + ch * 16) = v;
            }
        }
        __syncthreads();

        float acc[2][NF][4];
#pragma unroll
        for (int mi = 0; mi < 2; mi++)
#pragma unroll
            for (int nf = 0; nf < NF; nf++)
#pragma unroll
                for (int q = 0; q < 4; q++) acc[mi][nf][q] = 0.0f;

#pragma unroll
        for (int ks = 0; ks < 8; ks++) {
            uint32_t koff = ks * 32;
            uint32_t a[2][4];
            ldsm4(a[0], a_addr0 + koff);
            ldsm4(a[1], a_addr0 + 16 * PITCH + koff);
            uint32_t bh[NF][2], bl[NF][2];
#pragma unroll
            for (int pr = 0; pr < NF / 2; pr++) {
                uint32_t r[4];
                ldsm4(r, b_addr0 + pr * 16 * PITCH + koff);
                bh[2 * pr][0] = r[0]; bh[2 * pr][1] = r[1];
                bh[2 * pr + 1][0] = r[2]; bh[2 * pr + 1][1] = r[3];
                ldsm4(r, b_addr0 + (BL - BH) + pr * 16 * PITCH + koff);
                bl[2 * pr][0] = r[0]; bl[2 * pr][1] = r[1];
                bl[2 * pr + 1][0] = r[2]; bl[2 * pr + 1][1] = r[3];
            }
#pragma unroll
            for (int mi = 0; mi < 2; mi++)
#pragma unroll
                for (int nf = 0; nf < NF; nf++) {
                    mma_f16(acc[mi][nf], a[mi], bh[nf]);
                    mma_f16(acc[mi][nf], a[mi], bl[nf]);
                }
        }

        // ---- epilogue: fp16 stores ----
#pragma unroll
        for (int mi = 0; mi < 2; mi++) {
            int r0 = mbase + m0 + mi * 16 + (lane >> 2);
#pragma unroll
            for (int nf = 0; nf < NF; nf++) {
                int col = n0 + nf * 8 + 2 * (lane & 3);
                if (r0 < n) {
                    __half2 v = __floats2half2_rn(acc[mi][nf][0], acc[mi][nf][1]);
                    *(__half2*)(G + (size_t)r0 * NC + col) = v;
                }
                if (r0 + 8 < n) {
                    __half2 v = __floats2half2_rn(acc[mi][nf][2], acc[mi][nf][3]);
                    *(__half2*)(G + (size_t)(r0 + 8) * NC + col) = v;
                }
            }
        }
        __syncthreads();
    }
}

// -------- aggregation: OUT[i] = act(dinv[i]*(sum_j dinv[j]*G[j] + dinv[i]*G[i]) + bias)
template <int NC, bool RELU, typename OutT>
__global__ __launch_bounds__(256) void k_agg(
    const __half* __restrict__ G, const float* __restrict__ bias,
    OutT* __restrict__ OUT, int n)
{
    constexpr int V = NC / 32;
    constexpr int V2 = V / 2;
    int gw = (blockIdx.x * blockDim.x + threadIdx.x) >> 5;
    int lane = threadIdx.x & 31;
    if (gw >= n) return;

    float di = g_dinv[gw];

    float acc[V];
    {
        const __half2* ps = (const __half2*)(G + (size_t)gw * NC + lane * V);
#pragma unroll
        for (int q = 0; q < V2; q++) {
            float2 fv = __half22float2(ps[q]);
            acc[2 * q] = di * fv.x;
            acc[2 * q + 1] = di * fv.y;
        }
    }

    int s = g_rptr[gw], e = g_rptr[gw + 1];
    for (int base = s; base < e; base += 32) {
        int idx = base + lane;
        int sj = 0;
        float dj = 0.0f;
        if (idx < e) {
            sj = g_csr[idx];
            dj = g_dinv[sj];
        }
        int m = e - base; if (m > 32) m = 32;
        int j = 0;
        for (; j + 4 <= m; j += 4) {
            int s0 = __shfl_sync(0xffffffffu, sj, j);
            int s1 = __shfl_sync(0xffffffffu, sj, j + 1);
            int s2 = __shfl_sync(0xffffffffu, sj, j + 2);
            int s3 = __shfl_sync(0xffffffffu, sj, j + 3);
            float d0 = __shfl_sync(0xffffffffu, dj, j);
            float d1 = __shfl_sync(0xffffffffu, dj, j + 1);
            float d2 = __shfl_sync(0xffffffffu, dj, j + 2);
            float d3 = __shfl_sync(0xffffffffu, dj, j + 3);
            const __half2* p0 = (const __half2*)(G + (size_t)s0 * NC + lane * V);
            const __half2* p1 = (const __half2*)(G + (size_t)s1 * NC + lane * V);
            const __half2* p2 = (const __half2*)(G + (size_t)s2 * NC + lane * V);
            const __half2* p3 = (const __half2*)(G + (size_t)s3 * NC + lane * V);
#pragma unroll
            for (int q = 0; q < V2; q++) {
                float2 a = __half22float2(p0[q]);
                float2 b = __half22float2(p1[q]);
                float2 c = __half22float2(p2[q]);
                float2 d = __half22float2(p3[q]);
                acc[2 * q]     += d0 * a.x + d1 * b.x + d2 * c.x + d3 * d.x;
                acc[2 * q + 1] += d0 * a.y + d1 * b.y + d2 * c.y + d3 * d.y;
            }
        }
        for (; j < m; j++) {
            int s0 = __shfl_sync(0xffffffffu, sj, j);
            float d0 = __shfl_sync(0xffffffffu, dj, j);
            const __half2* p = (const __half2*)(G + (size_t)s0 * NC + lane * V);
#pragma unroll
            for (int q = 0; q < V2; q++) {
                float2 a = __half22float2(p[q]);
                acc[2 * q]     += d0 * a.x;
                acc[2 * q + 1] += d0 * a.y;
            }
        }
    }

    float bv[V];
#pragma unroll
    for (int q = 0; q < V2; q++) {
        float2 b = *(const float2*)(bias + lane * V + 2 * q);
        bv[2 * q] = b.x; bv[2 * q + 1] = b.y;
    }
    float r[V];
#pragma unroll
    for (int v = 0; v < V; v++) {
        r[v] = acc[v] * di + bv[v];
        if (RELU) r[v] = fmaxf(r[v], 0.0f);
    }
    if constexpr (sizeof(OutT) == 2) {
        __half2* po = (__half2*)((__half*)OUT + (size_t)gw * NC + lane * V);
#pragma unroll
        for (int q = 0; q < V2; q++)
            po[q] = __floats2half2_rn(r[2 * q], r[2 * q + 1]);
    } else {
        float* po = (float*)OUT + (size_t)gw * NC + lane * V;
#pragma unroll
        for (int q = 0; q < V2; q++) {
            float2 o; o.x = r[2 * q]; o.y = r[2 * q + 1];
            *(float2*)(po + 2 * q) = o;
        }
    }
}

// ---------------- launch ----------------
extern "C" void kernel_launch(void* const* d_in, const int* in_sizes, int n_in,
                              void* d_out, int out_size)
{
    const float* x  = (const float*)d_in[0];
    const void*  ei = d_in[1];
    const float* W1 = (const float*)d_in[2];
    const float* b1 = (const float*)d_in[3];
    const float* W2 = (const float*)d_in[4];
    const float* b2 = (const float*)d_in[5];
    float* out = (float*)d_out;

    int n = in_sizes[0] / IN_DIM;
    int E = in_sizes[1] / 2;

    __half *g1p, *h1p, *g2p, *w1s, *w2s;
    cudaGetSymbolAddress((void**)&g1p, g_g1);
    cudaGetSymbolAddress((void**)&h1p, g_h1);
    cudaGetSymbolAddress((void**)&g2p, g_g2);
    cudaGetSymbolAddress((void**)&w1s, g_w1s);
    cudaGetSymbolAddress((void**)&w2s, g_w2s);

    const int smem1 = 64 * 272 + 2 * 128 * 272;   // 87040 -> 2 CTAs/SM
    const int smem2 = 64 * 272 + 2 * 64 * 272;    // 52224 -> 4 CTAs/SM
    cudaFuncSetAttribute((const void*)k_gemm<HID_DIM, float>,
                         cudaFuncAttributeMaxDynamicSharedMemorySize, smem1);
    cudaFuncSetAttribute((const void*)k_gemm<OUT_DIM, __half>,
                         cudaFuncAttributeMaxDynamicSharedMemorySize, smem2);

    int nb1024 = (n + 1023) / 1024;
    int ntiles = (n + 63) / 64;
    int pg1 = (ntiles < 296) ? ntiles : 296;
    int pg2 = (ntiles < 592) ? ntiles : 592;
    int igrid = (n > HID_DIM * IN_DIM + OUT_DIM * HID_DIM ? n
                 : HID_DIM * IN_DIM + OUT_DIM * HID_DIM);

    k_init<<<(igrid + 255) / 256, 256>>>(W1, W2, n);                        // 0
    k_convcnt<<<(E + 255) / 256, 256>>>(ei, E);                             // 1
    k_scanA<<<nb1024, 1024>>>(n);                                           // 2
    k_gemm<HID_DIM, float><<<pg1, 256, smem1>>>(x, w1s, g1p, n, ntiles);    // 3 (ncu slot)
    k_scanC<<<(n + 255) / 256, 256>>>(n, E);                                // 4
    k_scatter<<<(E + 255) / 256, 256>>>(ei, E);                             // 5
    k_agg<HID_DIM, true, __half><<<(n * 32 + 255) / 256, 256>>>(g1p, b1, h1p, n);   // 6
    k_gemm<OUT_DIM, __half><<<pg2, 256, smem2>>>(h1p, w2s, g2p, n, ntiles); // 7
    k_agg<OUT_DIM, false, float><<<(n * 32 + 255) / 256, 256>>>(g2p, b2, out, n);   // 8
}